// round 8
// baseline (speedup 1.0000x reference)
#include <cuda_runtime.h>
#include <cuda_bf16.h>
#include <cstdint>

#define NATOMS 2048
#define CATOM  128

// ---------------- scratch (no allocations allowed) ----------------
__device__ float g_qn  [NATOMS*CATOM];
__device__ __align__(16) __nv_bfloat16 g_qh[NATOMS*CATOM];
__device__ __align__(16) __nv_bfloat16 g_kh[NATOMS*CATOM];
__device__ __align__(16) __nv_bfloat16 g_vh[NATOMS*CATOM];
__device__ float g_gate[NATOMS*CATOM];
__device__ float g_go  [NATOMS*CATOM];
__device__ float g_ql1 [NATOMS*CATOM];
__device__ float g_h   [NATOMS*4*CATOM];

// ---------------- mma helpers ----------------
__device__ __forceinline__ uint32_t packbf(float lo, float hi){
    uint32_t r; asm("cvt.rn.bf16x2.f32 %0, %1, %2;" : "=r"(r) : "f"(hi), "f"(lo)); return r;
}
__device__ __forceinline__ void mma16816(float* d, const uint32_t* a, const uint32_t* b){
    asm volatile("mma.sync.aligned.m16n8k16.row.col.f32.bf16.bf16.f32 "
        "{%0,%1,%2,%3}, {%4,%5,%6,%7}, {%8,%9}, {%0,%1,%2,%3};"
        : "+f"(d[0]),"+f"(d[1]),"+f"(d[2]),"+f"(d[3])
        : "r"(a[0]),"r"(a[1]),"r"(a[2]),"r"(a[3]), "r"(b[0]),"r"(b[1]));
}
__device__ __forceinline__ void ldmx4(uint32_t* r, uint32_t addr){
    asm volatile("ldmatrix.sync.aligned.m8n8.x4.shared.b16 {%0,%1,%2,%3}, [%4];"
        : "=r"(r[0]),"=r"(r[1]),"=r"(r[2]),"=r"(r[3]) : "r"(addr));
}
__device__ __forceinline__ void ldmx4t(uint32_t* r, uint32_t addr){
    asm volatile("ldmatrix.sync.aligned.m8n8.x4.trans.shared.b16 {%0,%1,%2,%3}, [%4];"
        : "=r"(r[0]),"=r"(r[1]),"=r"(r[2]),"=r"(r[3]) : "r"(addr));
}
// byte offset of (row, 16B-chunk): rows of 128 bf16 (256B), XOR swizzle
__device__ __forceinline__ uint32_t swz(int row, int ch){
    return (uint32_t)(row*256 + (((ch ^ (row & 7)) & 15) << 4));
}

// ---------------- LayerNorm over C=128 ----------------
__global__ __launch_bounds__(128) void ln_kernel(
    const float* __restrict__ x, const float* __restrict__ w,
    const float* __restrict__ b, float* __restrict__ y)
{
    int row = blockIdx.x;
    int t = threadIdx.x;
    float v = x[(size_t)row*CATOM + t];
    float s = v, s2 = v*v;
    #pragma unroll
    for (int o = 16; o > 0; o >>= 1) {
        s  += __shfl_xor_sync(0xffffffffu, s,  o);
        s2 += __shfl_xor_sync(0xffffffffu, s2, o);
    }
    __shared__ float ps[4], ps2[4];
    int warp = t >> 5;
    if ((t & 31) == 0) { ps[warp] = s; ps2[warp] = s2; }
    __syncthreads();
    float sum  = ps[0]  + ps[1]  + ps[2]  + ps[3];
    float sum2 = ps2[0] + ps2[1] + ps2[2] + ps2[3];
    float mu   = sum  * (1.f/CATOM);
    float var  = sum2 * (1.f/CATOM) - mu*mu;
    float rstd = rsqrtf(var + 1e-5f);
    y[(size_t)row*CATOM + t] = (v - mu) * rstd * w[t] + b[t];
}

// ---------------- fp32 GEMM core: 64x64 tile, C = A @ B^T ----------------
__device__ __forceinline__ void gemm_core64(
    const float* __restrict__ A, const float* __restrict__ B,
    int K, float acc[4][4], float As[16][68], float Bs[16][68])
{
    const int tid = threadIdx.x;
    const int tx = tid & 15, ty = tid >> 4;
    const int m0 = blockIdx.y * 64, n0 = blockIdx.x * 64;
    const int row = tid >> 2;
    const int c4  = (tid & 3) * 4;
    for (int k0 = 0; k0 < K; k0 += 16) {
        float4 a  = *(const float4*)&A[(size_t)(m0+row)*K + k0 + c4];
        float4 bb = *(const float4*)&B[(size_t)(n0+row)*K + k0 + c4];
        As[c4+0][row] = a.x;  As[c4+1][row] = a.y;  As[c4+2][row] = a.z;  As[c4+3][row] = a.w;
        Bs[c4+0][row] = bb.x; Bs[c4+1][row] = bb.y; Bs[c4+2][row] = bb.z; Bs[c4+3][row] = bb.w;
        __syncthreads();
        #pragma unroll
        for (int kk = 0; kk < 16; kk++) {
            float av[4], bv[4];
            #pragma unroll
            for (int i = 0; i < 4; i++) { av[i] = As[kk][ty + 16*i]; bv[i] = Bs[kk][tx + 16*i]; }
            #pragma unroll
            for (int i = 0; i < 4; i++)
                #pragma unroll
                for (int j = 0; j < 4; j++)
                    acc[i][j] = fmaf(av[i], bv[j], acc[i][j]);
        }
        __syncthreads();
    }
}

// 64x64-tile GEMM (W1): op 2 = relu
__global__ __launch_bounds__(256) void gemm_nt(
    const float* __restrict__ A, const float* __restrict__ B,
    const float* __restrict__ bias, const float* __restrict__ resid,
    float* __restrict__ C, int N, int K, int op)
{
    __shared__ float As[16][68];
    __shared__ float Bs[16][68];
    float acc[4][4];
    #pragma unroll
    for (int i = 0; i < 4; i++)
        #pragma unroll
        for (int j = 0; j < 4; j++) acc[i][j] = 0.f;
    gemm_core64(A, B, K, acc, As, Bs);
    const int tid = threadIdx.x;
    const int tx = tid & 15, ty = tid >> 4;
    const int m0 = blockIdx.y * 64, n0 = blockIdx.x * 64;
    #pragma unroll
    for (int i = 0; i < 4; i++) {
        int mm = m0 + ty + 16*i;
        #pragma unroll
        for (int j = 0; j < 4; j++) {
            int nn = n0 + tx + 16*j;
            float v = acc[i][j];
            if (bias)    v += bias[nn];
            if (op == 2) v = fmaxf(v, 0.f);
            if (resid)   v += resid[(size_t)mm*N + nn];
            C[(size_t)mm*N + nn] = v;
        }
    }
}

// QKVG projection with bf16 epilogues (q pre-scaled by 1/sqrt(32))
__global__ __launch_bounds__(256) void gemm_qkvg(
    const float* __restrict__ Wq, const float* __restrict__ bq,
    const float* __restrict__ Wk, const float* __restrict__ Wv,
    const float* __restrict__ Wg)
{
    __shared__ float As[16][68];
    __shared__ float Bs[16][68];
    int z = blockIdx.z;
    const float* B = (z==0) ? Wq : (z==1) ? Wk : (z==2) ? Wv : Wg;
    float acc[4][4];
    #pragma unroll
    for (int i = 0; i < 4; i++)
        #pragma unroll
        for (int j = 0; j < 4; j++) acc[i][j] = 0.f;
    gemm_core64(g_qn, B, CATOM, acc, As, Bs);
    const int tid = threadIdx.x;
    const int tx = tid & 15, ty = tid >> 4;
    const int m0 = blockIdx.y * 64, n0 = blockIdx.x * 64;
    #pragma unroll
    for (int i = 0; i < 4; i++) {
        int mm = m0 + ty + 16*i;
        #pragma unroll
        for (int j = 0; j < 4; j++) {
            int nn = n0 + tx + 16*j;
            float v = acc[i][j];
            size_t idx = (size_t)mm*CATOM + nn;
            if (z == 0)      g_qh[idx] = __float2bfloat16((v + bq[nn]) * 0.17677669529663687f);
            else if (z == 1) g_kh[idx] = __float2bfloat16(v);
            else if (z == 2) g_vh[idx] = __float2bfloat16(v);
            else             g_gate[idx] = 1.f / (1.f + __expf(-v));
        }
    }
}

// 32x64-tile GEMM for N=128 epilogue GEMMs (128 CTAs)
__global__ __launch_bounds__(256) void gemm_nt32(
    const float* __restrict__ A, const float* __restrict__ B,
    const float* __restrict__ bias, const float* __restrict__ resid,
    float* __restrict__ C, int N, int K)
{
    __shared__ float As[16][36];
    __shared__ float Bs[16][68];
    const int tid = threadIdx.x;
    const int tx = tid & 15, ty = tid >> 4;
    const int m0 = blockIdx.y * 32, n0 = blockIdx.x * 64;
    float acc[2][4];
    #pragma unroll
    for (int i = 0; i < 2; i++)
        #pragma unroll
        for (int j = 0; j < 4; j++) acc[i][j] = 0.f;
    const int arow = tid >> 2;
    const int c4   = (tid & 3) * 4;
    for (int k0 = 0; k0 < K; k0 += 16) {
        if (tid < 128) {
            float4 a = *(const float4*)&A[(size_t)(m0+arow)*K + k0 + c4];
            As[c4+0][arow] = a.x; As[c4+1][arow] = a.y; As[c4+2][arow] = a.z; As[c4+3][arow] = a.w;
        }
        float4 bb = *(const float4*)&B[(size_t)(n0+arow)*K + k0 + c4];
        Bs[c4+0][arow] = bb.x; Bs[c4+1][arow] = bb.y; Bs[c4+2][arow] = bb.z; Bs[c4+3][arow] = bb.w;
        __syncthreads();
        #pragma unroll
        for (int kk = 0; kk < 16; kk++) {
            float a0 = As[kk][ty], a1 = As[kk][ty+16];
            float bv[4];
            #pragma unroll
            for (int j = 0; j < 4; j++) bv[j] = Bs[kk][tx + 16*j];
            #pragma unroll
            for (int j = 0; j < 4; j++) {
                acc[0][j] = fmaf(a0, bv[j], acc[0][j]);
                acc[1][j] = fmaf(a1, bv[j], acc[1][j]);
            }
        }
        __syncthreads();
    }
    #pragma unroll
    for (int i = 0; i < 2; i++) {
        int mm = m0 + ty + 16*i;
        #pragma unroll
        for (int j = 0; j < 4; j++) {
            int nn = n0 + tx + 16*j;
            float v = acc[i][j];
            if (bias)  v += bias[nn];
            if (resid) v += resid[(size_t)mm*N + nn];
            C[(size_t)mm*N + nn] = v;
        }
    }
}

// ---------------- tensor-core flash attention with pair bias ----------------
// dynamic smem layout (bytes)
#define KS_OFF    0u        // 64*256      = 16384
#define VS_OFF    16384u    // 64*256      = 16384
#define QS_OFF    32768u    // 16*256      = 4096
#define BIAS_OFF  36864u    // 4*16*68*4   = 17408
#define OBUF_OFF  54272u    // 4*16*33*4   = 8448
#define WW_OFF    62720u    // 64*4        = 256
#define WSUM_OFF  62976u
#define WCS_OFF   62992u
#define STAT_OFF  63008u    // 16*16*2*4   = 2048
#define ATTN_SMEM 65056u

__global__ __launch_bounds__(512,1) void attn_mma(
    const float* __restrict__ plm,  const float* __restrict__ beta,
    const float* __restrict__ npw,  const float* __restrict__ npb,
    const float* __restrict__ Wpb)
{
    extern __shared__ char smem_raw[];
    char* k_sb = smem_raw + KS_OFF;
    char* v_sb = smem_raw + VS_OFF;
    char* q_sb = smem_raw + QS_OFF;
    float* bias_s = (float*)(smem_raw + BIAS_OFF);
    float* obuf   = (float*)(smem_raw + OBUF_OFF);
    float* ww_s   = (float*)(smem_raw + WW_OFF);
    float* wsum_s = (float*)(smem_raw + WSUM_OFF);
    float* wcs_s  = (float*)(smem_raw + WCS_OFF);
    float* stat_s = (float*)(smem_raw + STAT_OFF);   // [16 warps][16 rows][2]

    const int tid  = threadIdx.x;
    const int lane = tid & 31, wid = tid >> 5;
    const int h = wid & 3, kq = wid >> 2;
    const int i0 = blockIdx.x * 16;

    if (tid < 64) ww_s[tid] = npw[tid & 15] * Wpb[tid];
    if (tid < 4) {
        float sw = 0.f, sc = 0.f;
        #pragma unroll
        for (int c = 0; c < 16; c++) {
            float t = npw[c] * Wpb[tid*16 + c];
            sw += t;
            sc += npb[c] * Wpb[tid*16 + c];
        }
        wsum_s[tid] = sw; wcs_s[tid] = sc;
    }
    // stage Q tile
    if (tid < 256) {
        int row = tid >> 4, ch = tid & 15;
        *(uint4*)(q_sb + swz(row, ch)) = *(const uint4*)&g_qh[(size_t)(i0+row)*CATOM + ch*8];
    }
    __syncthreads();

    // Q A-fragments (persist)
    uint32_t qa[2][4];
    {
        uint32_t qb = (uint32_t)__cvta_generic_to_shared(q_sb);
        int row = (lane & 7) + ((lane >> 3) & 1) * 8;
        #pragma unroll
        for (int kc = 0; kc < 2; kc++)
            ldmx4(qa[kc], qb + swz(row, h*4 + kc*2 + (lane >> 4)));
    }
    // K/V ldmatrix addresses (fixed across tiles)
    uint32_t kaddr[2], vaddr[2];
    {
        uint32_t kb = (uint32_t)__cvta_generic_to_shared(k_sb);
        uint32_t vb = (uint32_t)__cvta_generic_to_shared(v_sb);
        int krow = kq*16 + (lane & 7) + ((lane >> 4) & 1) * 8;
        int vrow = kq*16 + (lane & 7) + ((lane >> 3) & 1) * 8;
        #pragma unroll
        for (int kc = 0; kc < 2; kc++) kaddr[kc] = kb + swz(krow, h*4 + kc*2 + ((lane >> 3) & 1));
        #pragma unroll
        for (int vp = 0; vp < 2; vp++) vaddr[vp] = vb + swz(vrow, h*4 + vp*2 + (lane >> 4));
    }

    const int r0 = lane >> 2;        // fragment row (0..7); second row = r0+8
    float m0 = -1e30f, m1 = -1e30f, l0 = 0.f, l1 = 0.f;
    float o[4][4];
    #pragma unroll
    for (int nd = 0; nd < 4; nd++)
        #pragma unroll
        for (int e = 0; e < 4; e++) o[nd][e] = 0.f;

    for (int jt = 0; jt < 32; jt++) {
        const int j0 = jt * 64;
        // ---- stage K/V (64 keys) ----
        #pragma unroll
        for (int s = 0; s < 2; s++) {
            int sl = tid + s*512;
            int row = sl >> 4, ch = sl & 15;
            uint32_t off = swz(row, ch);
            *(uint4*)(k_sb + off) = *(const uint4*)&g_kh[(size_t)(j0+row)*CATOM + ch*8];
            *(uint4*)(v_sb + off) = *(const uint4*)&g_vh[(size_t)(j0+row)*CATOM + ch*8];
        }
        // ---- pair bias: 2 pairs per thread, loads front-batched ----
        {
            int ia = tid, ib = tid + 512;
            int ra = ia >> 6, ka = ia & 63;
            int rb = ib >> 6, kb2 = ib & 63;
            const float4* pa_ = (const float4*)(plm + ((size_t)(i0+ra)*NATOMS + (j0+ka))*16);
            const float4* pb_ = (const float4*)(plm + ((size_t)(i0+rb)*NATOMS + (j0+kb2))*16);
            float4 xa[4], xb[4];
            #pragma unroll
            for (int t = 0; t < 4; t++) { xa[t] = pa_[t]; xb[t] = pb_[t]; }
            float bma = beta[(size_t)(i0+ra)*NATOMS + j0 + ka];
            float bmb = beta[(size_t)(i0+rb)*NATOMS + j0 + kb2];
            #pragma unroll
            for (int pp = 0; pp < 2; pp++) {
                float4* x4 = pp ? xb : xa;
                float bm  = pp ? bmb : bma;
                int row   = pp ? rb : ra;
                int key   = pp ? kb2 : ka;
                float sum = 0.f, sum2 = 0.f;
                #pragma unroll
                for (int t = 0; t < 4; t++) {
                    sum += x4[t].x + x4[t].y + x4[t].z + x4[t].w;
                    sum2 = fmaf(x4[t].x, x4[t].x, sum2);
                    sum2 = fmaf(x4[t].y, x4[t].y, sum2);
                    sum2 = fmaf(x4[t].z, x4[t].z, sum2);
                    sum2 = fmaf(x4[t].w, x4[t].w, sum2);
                }
                float mu   = sum * 0.0625f;
                float rstd = rsqrtf(fmaf(-mu, mu, sum2 * 0.0625f) + 1e-5f);
                #pragma unroll
                for (int hh = 0; hh < 4; hh++) {
                    float d = 0.f;
                    #pragma unroll
                    for (int t = 0; t < 4; t++) {
                        float4 w4 = ((const float4*)ww_s)[hh*4 + t];
                        d = fmaf(x4[t].x, w4.x, d);
                        d = fmaf(x4[t].y, w4.y, d);
                        d = fmaf(x4[t].z, w4.z, d);
                        d = fmaf(x4[t].w, w4.w, d);
                    }
                    bias_s[hh*1088 + row*68 + key] =
                        fmaf(rstd, d - mu*wsum_s[hh], wcs_s[hh] + bm);
                }
            }
        }
        __syncthreads();

        // ---- QK^T : 16 rows x 16 keys for this warp ----
        float c[2][4];
        #pragma unroll
        for (int n = 0; n < 2; n++)
            #pragma unroll
            for (int e = 0; e < 4; e++) c[n][e] = 0.f;
        #pragma unroll
        for (int kc = 0; kc < 2; kc++) {
            uint32_t b[4];
            ldmx4(b, kaddr[kc]);
            mma16816(c[0], qa[kc], b + 0);
            mma16816(c[1], qa[kc], b + 2);
        }
        // add pair bias + beta
        float rmax0 = -1e30f, rmax1 = -1e30f;
        #pragma unroll
        for (int n = 0; n < 2; n++) {
            int key = kq*16 + n*8 + (lane & 3)*2;
            const float* bp = bias_s + h*1088 + r0*68 + key;
            c[n][0] += bp[0];       c[n][1] += bp[1];
            c[n][2] += bp[8*68];    c[n][3] += bp[8*68 + 1];
            rmax0 = fmaxf(rmax0, fmaxf(c[n][0], c[n][1]));
            rmax1 = fmaxf(rmax1, fmaxf(c[n][2], c[n][3]));
        }
        rmax0 = fmaxf(rmax0, __shfl_xor_sync(0xffffffffu, rmax0, 1));
        rmax0 = fmaxf(rmax0, __shfl_xor_sync(0xffffffffu, rmax0, 2));
        rmax1 = fmaxf(rmax1, __shfl_xor_sync(0xffffffffu, rmax1, 1));
        rmax1 = fmaxf(rmax1, __shfl_xor_sync(0xffffffffu, rmax1, 2));
        float M0n = fmaxf(m0, rmax0), M1n = fmaxf(m1, rmax1);
        float cor0 = __expf(m0 - M0n), cor1 = __expf(m1 - M1n);
        m0 = M0n; m1 = M1n;
        l0 *= cor0; l1 *= cor1;
        #pragma unroll
        for (int nd = 0; nd < 4; nd++) {
            o[nd][0] *= cor0; o[nd][1] *= cor0;
            o[nd][2] *= cor1; o[nd][3] *= cor1;
        }
        // exp + pack P to bf16 A-fragment
        float s0 = 0.f, s1 = 0.f;
        uint32_t pa2[4];
        #pragma unroll
        for (int n = 0; n < 2; n++) {
            float p0 = __expf(c[n][0] - m0), p1 = __expf(c[n][1] - m0);
            float p2 = __expf(c[n][2] - m1), p3 = __expf(c[n][3] - m1);
            s0 += p0 + p1; s1 += p2 + p3;
            pa2[n*2 + 0] = packbf(p0, p1);
            pa2[n*2 + 1] = packbf(p2, p3);
        }
        // NOTE frag order must be a0=rows0-7/k0-7, a1=rows8-15/k0-7, a2=rows0-7/k8-15, a3=rows8-15/k8-15
        { uint32_t t = pa2[1]; pa2[1] = pa2[1]; (void)t; } // a-order already: [p(n0,r0) p(n0,r1) p(n1,r0) p(n1,r1)]
        s0 += __shfl_xor_sync(0xffffffffu, s0, 1);
        s0 += __shfl_xor_sync(0xffffffffu, s0, 2);
        s1 += __shfl_xor_sync(0xffffffffu, s1, 1);
        s1 += __shfl_xor_sync(0xffffffffu, s1, 2);
        l0 += s0; l1 += s1;
        // ---- P @ V ----
        #pragma unroll
        for (int vp = 0; vp < 2; vp++) {
            uint32_t b[4];
            ldmx4t(b, vaddr[vp]);
            mma16816(o[vp*2 + 0], pa2, b + 0);
            mma16816(o[vp*2 + 1], pa2, b + 2);
        }
        __syncthreads();
    }

    // ---- combine the 4 key-quarter warps per head ----
    if ((lane & 3) == 0) {
        stat_s[(wid*16 + r0    )*2 + 0] = m0;
        stat_s[(wid*16 + r0    )*2 + 1] = l0;
        stat_s[(wid*16 + r0 + 8)*2 + 0] = m1;
        stat_s[(wid*16 + r0 + 8)*2 + 1] = l1;
    }
    __syncthreads();
    float M0 = -1e30f, M1 = -1e30f;
    #pragma unroll
    for (int q = 0; q < 4; q++) {
        M0 = fmaxf(M0, stat_s[((q*4 + h)*16 + r0    )*2]);
        M1 = fmaxf(M1, stat_s[((q*4 + h)*16 + r0 + 8)*2]);
    }
    float L0 = 0.f, L1 = 0.f;
    #pragma unroll
    for (int q = 0; q < 4; q++) {
        L0 += stat_s[((q*4+h)*16 + r0    )*2 + 1] * __expf(stat_s[((q*4+h)*16 + r0    )*2] - M0);
        L1 += stat_s[((q*4+h)*16 + r0 + 8)*2 + 1] * __expf(stat_s[((q*4+h)*16 + r0 + 8)*2] - M1);
    }
    float fac0 = __expf(m0 - M0), fac1 = __expf(m1 - M1);
    #pragma unroll
    for (int nd = 0; nd < 4; nd++) {
        o[nd][0] *= fac0; o[nd][1] *= fac0;
        o[nd][2] *= fac1; o[nd][3] *= fac1;
    }
    // staged O reduction: kq0 writes, kq1/2 add, kq3 finalizes
    #pragma unroll
    for (int ph = 0; ph < 3; ph++) {
        if (kq == ph) {
            #pragma unroll
            for (int nd = 0; nd < 4; nd++) {
                int d0 = nd*8 + (lane & 3)*2;
                float* ob = obuf + h*528 + r0*33 + d0;
                if (ph == 0) {
                    ob[0] = o[nd][0]; ob[1] = o[nd][1];
                    ob[8*33] = o[nd][2]; ob[8*33+1] = o[nd][3];
                } else {
                    ob[0] += o[nd][0]; ob[1] += o[nd][1];
                    ob[8*33] += o[nd][2]; ob[8*33+1] += o[nd][3];
                }
            }
        }
        __syncthreads();
    }
    if (kq == 3) {
        float inv0 = 1.f / L0, inv1 = 1.f / L1;
        int rowa = i0 + r0, rowb = i0 + r0 + 8;
        #pragma unroll
        for (int nd = 0; nd < 4; nd++) {
            int d0 = nd*8 + (lane & 3)*2;
            int col = h*32 + d0;
            const float* ob = obuf + h*528 + r0*33 + d0;
            float v00 = (ob[0]      + o[nd][0]) * inv0;
            float v01 = (ob[1]      + o[nd][1]) * inv0;
            float v10 = (ob[8*33]   + o[nd][2]) * inv1;
            float v11 = (ob[8*33+1] + o[nd][3]) * inv1;
            g_go[(size_t)rowa*CATOM + col    ] = v00 * g_gate[(size_t)rowa*CATOM + col    ];
            g_go[(size_t)rowa*CATOM + col + 1] = v01 * g_gate[(size_t)rowa*CATOM + col + 1];
            g_go[(size_t)rowb*CATOM + col    ] = v10 * g_gate[(size_t)rowb*CATOM + col    ];
            g_go[(size_t)rowb*CATOM + col + 1] = v11 * g_gate[(size_t)rowb*CATOM + col + 1];
        }
    }
}

// ---------------- host launch ----------------
extern "C" void kernel_launch(void* const* d_in, const int* in_sizes, int n_in,
                              void* d_out, int out_size)
{
    const float* ql  = (const float*)d_in[0];
    const float* plm = (const float*)d_in[2];
    const float* beta= (const float*)d_in[3];
    const float* nqw = (const float*)d_in[4];
    const float* nqb = (const float*)d_in[5];
    const float* npw = (const float*)d_in[6];
    const float* npb = (const float*)d_in[7];
    const float* Wq  = (const float*)d_in[8];
    const float* bq  = (const float*)d_in[9];
    const float* Wk  = (const float*)d_in[10];
    const float* Wv  = (const float*)d_in[11];
    const float* Wpb = (const float*)d_in[12];
    const float* Wg  = (const float*)d_in[13];
    const float* Wo  = (const float*)d_in[14];
    const float* tlw = (const float*)d_in[15];
    const float* tlb = (const float*)d_in[16];
    const float* W1  = (const float*)d_in[17];
    const float* b1  = (const float*)d_in[18];
    const float* W2  = (const float*)d_in[19];
    const float* b2  = (const float*)d_in[20];

    float *qn, *go, *ql1, *hh;
    cudaGetSymbolAddress((void**)&qn,  g_qn);
    cudaGetSymbolAddress((void**)&go,  g_go);
    cudaGetSymbolAddress((void**)&ql1, g_ql1);
    cudaGetSymbolAddress((void**)&hh,  g_h);

    cudaFuncSetAttribute(attn_mma, cudaFuncAttributeMaxDynamicSharedMemorySize, ATTN_SMEM);

    // 1. ql_norm
    ln_kernel<<<NATOMS, 128>>>(ql, nqw, nqb, qn);
    // 2. q(bf16,scaled), k(bf16), v(bf16), gate(sigmoid)
    gemm_qkvg<<<dim3(2, 32, 4), 256>>>(Wq, bq, Wk, Wv, Wg);
    // 3. pair-biased flash attention -> g_go = gate * attn_out
    attn_mma<<<NATOMS/16, 512, ATTN_SMEM>>>(plm, beta, npw, npb, Wpb);
    // 4. ql1 = ql + go @ Wo^T
    gemm_nt32<<<dim3(2, 64), 256>>>(go, Wo, nullptr, ql, ql1, CATOM, CATOM);
    // 5. t = LN(ql1)
    ln_kernel<<<NATOMS, 128>>>(ql1, tlw, tlb, qn);
    // 6. h = relu(t @ W1^T + b1)
    gemm_nt<<<dim3(8, 32), 256>>>(qn, W1, b1, nullptr, hh, 4*CATOM, CATOM, 2);
    // 7. out = ql1 + h @ W2^T + b2
    gemm_nt32<<<dim3(2, 64), 256>>>(hh, W2, b2, ql1, (float*)d_out, CATOM, 4*CATOM);
}

// round 9
// speedup vs baseline: 1.0048x; 1.0048x over previous
#include <cuda_runtime.h>
#include <cuda_bf16.h>
#include <cstdint>

#define NATOMS 2048
#define CATOM  128

// ---------------- scratch (no allocations allowed) ----------------
__device__ float g_qn  [NATOMS*CATOM];
__device__ __align__(16) __nv_bfloat16 g_qh[NATOMS*CATOM];
__device__ __align__(16) __nv_bfloat16 g_kh[NATOMS*CATOM];
__device__ __align__(16) __nv_bfloat16 g_vh[NATOMS*CATOM];
__device__ float g_gate[NATOMS*CATOM];
__device__ float g_go  [NATOMS*CATOM];
__device__ float g_ql1 [NATOMS*CATOM];
__device__ float g_h   [NATOMS*4*CATOM];

// ---------------- mma helpers ----------------
__device__ __forceinline__ uint32_t packbf(float lo, float hi){
    uint32_t r; asm("cvt.rn.bf16x2.f32 %0, %1, %2;" : "=r"(r) : "f"(hi), "f"(lo)); return r;
}
__device__ __forceinline__ void mma16816(float* d, const uint32_t* a, const uint32_t* b){
    asm volatile("mma.sync.aligned.m16n8k16.row.col.f32.bf16.bf16.f32 "
        "{%0,%1,%2,%3}, {%4,%5,%6,%7}, {%8,%9}, {%0,%1,%2,%3};"
        : "+f"(d[0]),"+f"(d[1]),"+f"(d[2]),"+f"(d[3])
        : "r"(a[0]),"r"(a[1]),"r"(a[2]),"r"(a[3]), "r"(b[0]),"r"(b[1]));
}
__device__ __forceinline__ void ldmx4(uint32_t* r, uint32_t addr){
    asm volatile("ldmatrix.sync.aligned.m8n8.x4.shared.b16 {%0,%1,%2,%3}, [%4];"
        : "=r"(r[0]),"=r"(r[1]),"=r"(r[2]),"=r"(r[3]) : "r"(addr));
}
__device__ __forceinline__ void ldmx4t(uint32_t* r, uint32_t addr){
    asm volatile("ldmatrix.sync.aligned.m8n8.x4.trans.shared.b16 {%0,%1,%2,%3}, [%4];"
        : "=r"(r[0]),"=r"(r[1]),"=r"(r[2]),"=r"(r[3]) : "r"(addr));
}
// byte offset of (row, 16B-chunk): rows of 128 bf16 (256B), XOR swizzle
__device__ __forceinline__ uint32_t swz(int row, int ch){
    return (uint32_t)(row*256 + (((ch ^ (row & 7)) & 15) << 4));
}

// ---------------- LayerNorm over C=128 ----------------
__global__ __launch_bounds__(128) void ln_kernel(
    const float* __restrict__ x, const float* __restrict__ w,
    const float* __restrict__ b, float* __restrict__ y)
{
    int row = blockIdx.x;
    int t = threadIdx.x;
    float v = x[(size_t)row*CATOM + t];
    float s = v, s2 = v*v;
    #pragma unroll
    for (int o = 16; o > 0; o >>= 1) {
        s  += __shfl_xor_sync(0xffffffffu, s,  o);
        s2 += __shfl_xor_sync(0xffffffffu, s2, o);
    }
    __shared__ float ps[4], ps2[4];
    int warp = t >> 5;
    if ((t & 31) == 0) { ps[warp] = s; ps2[warp] = s2; }
    __syncthreads();
    float sum  = ps[0]  + ps[1]  + ps[2]  + ps[3];
    float sum2 = ps2[0] + ps2[1] + ps2[2] + ps2[3];
    float mu   = sum  * (1.f/CATOM);
    float var  = sum2 * (1.f/CATOM) - mu*mu;
    float rstd = rsqrtf(var + 1e-5f);
    y[(size_t)row*CATOM + t] = (v - mu) * rstd * w[t] + b[t];
}

// ---------------- fp32 GEMM core: 64x64 tile, C = A @ B^T ----------------
__device__ __forceinline__ void gemm_core64(
    const float* __restrict__ A, const float* __restrict__ B,
    int K, float acc[4][4], float As[16][68], float Bs[16][68])
{
    const int tid = threadIdx.x;
    const int tx = tid & 15, ty = tid >> 4;
    const int m0 = blockIdx.y * 64, n0 = blockIdx.x * 64;
    const int row = tid >> 2;
    const int c4  = (tid & 3) * 4;
    for (int k0 = 0; k0 < K; k0 += 16) {
        float4 a  = *(const float4*)&A[(size_t)(m0+row)*K + k0 + c4];
        float4 bb = *(const float4*)&B[(size_t)(n0+row)*K + k0 + c4];
        As[c4+0][row] = a.x;  As[c4+1][row] = a.y;  As[c4+2][row] = a.z;  As[c4+3][row] = a.w;
        Bs[c4+0][row] = bb.x; Bs[c4+1][row] = bb.y; Bs[c4+2][row] = bb.z; Bs[c4+3][row] = bb.w;
        __syncthreads();
        #pragma unroll
        for (int kk = 0; kk < 16; kk++) {
            float av[4], bv[4];
            #pragma unroll
            for (int i = 0; i < 4; i++) { av[i] = As[kk][ty + 16*i]; bv[i] = Bs[kk][tx + 16*i]; }
            #pragma unroll
            for (int i = 0; i < 4; i++)
                #pragma unroll
                for (int j = 0; j < 4; j++)
                    acc[i][j] = fmaf(av[i], bv[j], acc[i][j]);
        }
        __syncthreads();
    }
}

// 64x64-tile GEMM (W1): op 2 = relu
__global__ __launch_bounds__(256) void gemm_nt(
    const float* __restrict__ A, const float* __restrict__ B,
    const float* __restrict__ bias, const float* __restrict__ resid,
    float* __restrict__ C, int N, int K, int op)
{
    __shared__ float As[16][68];
    __shared__ float Bs[16][68];
    float acc[4][4];
    #pragma unroll
    for (int i = 0; i < 4; i++)
        #pragma unroll
        for (int j = 0; j < 4; j++) acc[i][j] = 0.f;
    gemm_core64(A, B, K, acc, As, Bs);
    const int tid = threadIdx.x;
    const int tx = tid & 15, ty = tid >> 4;
    const int m0 = blockIdx.y * 64, n0 = blockIdx.x * 64;
    #pragma unroll
    for (int i = 0; i < 4; i++) {
        int mm = m0 + ty + 16*i;
        #pragma unroll
        for (int j = 0; j < 4; j++) {
            int nn = n0 + tx + 16*j;
            float v = acc[i][j];
            if (bias)    v += bias[nn];
            if (op == 2) v = fmaxf(v, 0.f);
            if (resid)   v += resid[(size_t)mm*N + nn];
            C[(size_t)mm*N + nn] = v;
        }
    }
}

// QKVG projection with bf16 epilogues (q pre-scaled by 1/sqrt(32))
__global__ __launch_bounds__(256) void gemm_qkvg(
    const float* __restrict__ Wq, const float* __restrict__ bq,
    const float* __restrict__ Wk, const float* __restrict__ Wv,
    const float* __restrict__ Wg)
{
    __shared__ float As[16][68];
    __shared__ float Bs[16][68];
    int z = blockIdx.z;
    const float* B = (z==0) ? Wq : (z==1) ? Wk : (z==2) ? Wv : Wg;
    float acc[4][4];
    #pragma unroll
    for (int i = 0; i < 4; i++)
        #pragma unroll
        for (int j = 0; j < 4; j++) acc[i][j] = 0.f;
    gemm_core64(g_qn, B, CATOM, acc, As, Bs);
    const int tid = threadIdx.x;
    const int tx = tid & 15, ty = tid >> 4;
    const int m0 = blockIdx.y * 64, n0 = blockIdx.x * 64;
    #pragma unroll
    for (int i = 0; i < 4; i++) {
        int mm = m0 + ty + 16*i;
        #pragma unroll
        for (int j = 0; j < 4; j++) {
            int nn = n0 + tx + 16*j;
            float v = acc[i][j];
            size_t idx = (size_t)mm*CATOM + nn;
            if (z == 0)      g_qh[idx] = __float2bfloat16((v + bq[nn]) * 0.17677669529663687f);
            else if (z == 1) g_kh[idx] = __float2bfloat16(v);
            else if (z == 2) g_vh[idx] = __float2bfloat16(v);
            else             g_gate[idx] = 1.f / (1.f + __expf(-v));
        }
    }
}

// 32x64-tile GEMM for N=128 epilogue GEMMs (128 CTAs)
__global__ __launch_bounds__(256) void gemm_nt32(
    const float* __restrict__ A, const float* __restrict__ B,
    const float* __restrict__ bias, const float* __restrict__ resid,
    float* __restrict__ C, int N, int K)
{
    __shared__ float As[16][36];
    __shared__ float Bs[16][68];
    const int tid = threadIdx.x;
    const int tx = tid & 15, ty = tid >> 4;
    const int m0 = blockIdx.y * 32, n0 = blockIdx.x * 64;
    float acc[2][4];
    #pragma unroll
    for (int i = 0; i < 2; i++)
        #pragma unroll
        for (int j = 0; j < 4; j++) acc[i][j] = 0.f;
    const int arow = tid >> 2;
    const int c4   = (tid & 3) * 4;
    for (int k0 = 0; k0 < K; k0 += 16) {
        if (tid < 128) {
            float4 a = *(const float4*)&A[(size_t)(m0+arow)*K + k0 + c4];
            As[c4+0][arow] = a.x; As[c4+1][arow] = a.y; As[c4+2][arow] = a.z; As[c4+3][arow] = a.w;
        }
        float4 bb = *(const float4*)&B[(size_t)(n0+arow)*K + k0 + c4];
        Bs[c4+0][arow] = bb.x; Bs[c4+1][arow] = bb.y; Bs[c4+2][arow] = bb.z; Bs[c4+3][arow] = bb.w;
        __syncthreads();
        #pragma unroll
        for (int kk = 0; kk < 16; kk++) {
            float a0 = As[kk][ty], a1 = As[kk][ty+16];
            float bv[4];
            #pragma unroll
            for (int j = 0; j < 4; j++) bv[j] = Bs[kk][tx + 16*j];
            #pragma unroll
            for (int j = 0; j < 4; j++) {
                acc[0][j] = fmaf(a0, bv[j], acc[0][j]);
                acc[1][j] = fmaf(a1, bv[j], acc[1][j]);
            }
        }
        __syncthreads();
    }
    #pragma unroll
    for (int i = 0; i < 2; i++) {
        int mm = m0 + ty + 16*i;
        #pragma unroll
        for (int j = 0; j < 4; j++) {
            int nn = n0 + tx + 16*j;
            float v = acc[i][j];
            if (bias)  v += bias[nn];
            if (resid) v += resid[(size_t)mm*N + nn];
            C[(size_t)mm*N + nn] = v;
        }
    }
}

// ---------------- tensor-core flash attention with pair bias ----------------
// dynamic smem layout (bytes)
#define KS_OFF    0u        // 64*256      = 16384
#define VS_OFF    16384u    // 64*256      = 16384
#define QS_OFF    32768u    // 16*256      = 4096
#define BIAS_OFF  36864u    // 4*16*68*4   = 17408
#define OBUF_OFF  54272u    // 4*16*33*4   = 8448
#define WW_OFF    62720u    // 64*4        = 256
#define WSUM_OFF  62976u
#define WCS_OFF   62992u
#define STAT_OFF  63008u    // 16*16*2*4   = 2048
#define ATTN_SMEM 65056u

__global__ __launch_bounds__(512,1) void attn_mma(
    const float* __restrict__ plm,  const float* __restrict__ beta,
    const float* __restrict__ npw,  const float* __restrict__ npb,
    const float* __restrict__ Wpb)
{
    extern __shared__ char smem_raw[];
    char* k_sb = smem_raw + KS_OFF;
    char* v_sb = smem_raw + VS_OFF;
    char* q_sb = smem_raw + QS_OFF;
    float* bias_s = (float*)(smem_raw + BIAS_OFF);
    float* obuf   = (float*)(smem_raw + OBUF_OFF);
    float* ww_s   = (float*)(smem_raw + WW_OFF);
    float* wsum_s = (float*)(smem_raw + WSUM_OFF);
    float* wcs_s  = (float*)(smem_raw + WCS_OFF);
    float* stat_s = (float*)(smem_raw + STAT_OFF);   // [16 warps][16 rows][2]

    const int tid  = threadIdx.x;
    const int lane = tid & 31, wid = tid >> 5;
    const int h = wid & 3, kq = wid >> 2;
    const int i0 = blockIdx.x * 16;

    if (tid < 64) ww_s[tid] = npw[tid & 15] * Wpb[tid];
    if (tid < 4) {
        float sw = 0.f, sc = 0.f;
        #pragma unroll
        for (int c = 0; c < 16; c++) {
            float t = npw[c] * Wpb[tid*16 + c];
            sw += t;
            sc += npb[c] * Wpb[tid*16 + c];
        }
        wsum_s[tid] = sw; wcs_s[tid] = sc;
    }
    // stage Q tile
    if (tid < 256) {
        int row = tid >> 4, ch = tid & 15;
        *(uint4*)(q_sb + swz(row, ch)) = *(const uint4*)&g_qh[(size_t)(i0+row)*CATOM + ch*8];
    }
    __syncthreads();

    // Q A-fragments (persist)
    uint32_t qa[2][4];
    {
        uint32_t qb = (uint32_t)__cvta_generic_to_shared(q_sb);
        int row = (lane & 7) + ((lane >> 3) & 1) * 8;
        #pragma unroll
        for (int kc = 0; kc < 2; kc++)
            ldmx4(qa[kc], qb + swz(row, h*4 + kc*2 + (lane >> 4)));
    }
    // K/V ldmatrix addresses (fixed across tiles)
    uint32_t kaddr[2], vaddr[2];
    {
        uint32_t kb = (uint32_t)__cvta_generic_to_shared(k_sb);
        uint32_t vb = (uint32_t)__cvta_generic_to_shared(v_sb);
        int krow = kq*16 + (lane & 7) + ((lane >> 4) & 1) * 8;
        int vrow = kq*16 + (lane & 7) + ((lane >> 3) & 1) * 8;
        #pragma unroll
        for (int kc = 0; kc < 2; kc++) kaddr[kc] = kb + swz(krow, h*4 + kc*2 + ((lane >> 3) & 1));
        #pragma unroll
        for (int vp = 0; vp < 2; vp++) vaddr[vp] = vb + swz(vrow, h*4 + vp*2 + (lane >> 4));
    }

    const int r0 = lane >> 2;        // fragment row (0..7); second row = r0+8
    float m0 = -1e30f, m1 = -1e30f, l0 = 0.f, l1 = 0.f;
    float o[4][4];
    #pragma unroll
    for (int nd = 0; nd < 4; nd++)
        #pragma unroll
        for (int e = 0; e < 4; e++) o[nd][e] = 0.f;

    for (int jt = 0; jt < 32; jt++) {
        const int j0 = jt * 64;
        // ---- stage K/V (64 keys) ----
        #pragma unroll
        for (int s = 0; s < 2; s++) {
            int sl = tid + s*512;
            int row = sl >> 4, ch = sl & 15;
            uint32_t off = swz(row, ch);
            *(uint4*)(k_sb + off) = *(const uint4*)&g_kh[(size_t)(j0+row)*CATOM + ch*8];
            *(uint4*)(v_sb + off) = *(const uint4*)&g_vh[(size_t)(j0+row)*CATOM + ch*8];
        }
        // ---- pair bias: 2 pairs per thread, loads front-batched ----
        {
            int ia = tid, ib = tid + 512;
            int ra = ia >> 6, ka = ia & 63;
            int rb = ib >> 6, kb2 = ib & 63;
            const float4* pa_ = (const float4*)(plm + ((size_t)(i0+ra)*NATOMS + (j0+ka))*16);
            const float4* pb_ = (const float4*)(plm + ((size_t)(i0+rb)*NATOMS + (j0+kb2))*16);
            float4 xa[4], xb[4];
            #pragma unroll
            for (int t = 0; t < 4; t++) { xa[t] = pa_[t]; xb[t] = pb_[t]; }
            float bma = beta[(size_t)(i0+ra)*NATOMS + j0 + ka];
            float bmb = beta[(size_t)(i0+rb)*NATOMS + j0 + kb2];
            #pragma unroll
            for (int pp = 0; pp < 2; pp++) {
                float4* x4 = pp ? xb : xa;
                float bm  = pp ? bmb : bma;
                int row   = pp ? rb : ra;
                int key   = pp ? kb2 : ka;
                float sum = 0.f, sum2 = 0.f;
                #pragma unroll
                for (int t = 0; t < 4; t++) {
                    sum += x4[t].x + x4[t].y + x4[t].z + x4[t].w;
                    sum2 = fmaf(x4[t].x, x4[t].x, sum2);
                    sum2 = fmaf(x4[t].y, x4[t].y, sum2);
                    sum2 = fmaf(x4[t].z, x4[t].z, sum2);
                    sum2 = fmaf(x4[t].w, x4[t].w, sum2);
                }
                float mu   = sum * 0.0625f;
                float rstd = rsqrtf(fmaf(-mu, mu, sum2 * 0.0625f) + 1e-5f);
                #pragma unroll
                for (int hh = 0; hh < 4; hh++) {
                    float d = 0.f;
                    #pragma unroll
                    for (int t = 0; t < 4; t++) {
                        float4 w4 = ((const float4*)ww_s)[hh*4 + t];
                        d = fmaf(x4[t].x, w4.x, d);
                        d = fmaf(x4[t].y, w4.y, d);
                        d = fmaf(x4[t].z, w4.z, d);
                        d = fmaf(x4[t].w, w4.w, d);
                    }
                    bias_s[hh*1088 + row*68 + key] =
                        fmaf(rstd, d - mu*wsum_s[hh], wcs_s[hh] + bm);
                }
            }
        }
        __syncthreads();

        // ---- QK^T : 16 rows x 16 keys for this warp ----
        float c[2][4];
        #pragma unroll
        for (int n = 0; n < 2; n++)
            #pragma unroll
            for (int e = 0; e < 4; e++) c[n][e] = 0.f;
        #pragma unroll
        for (int kc = 0; kc < 2; kc++) {
            uint32_t b[4];
            ldmx4(b, kaddr[kc]);
            mma16816(c[0], qa[kc], b + 0);
            mma16816(c[1], qa[kc], b + 2);
        }
        // add pair bias + beta
        float rmax0 = -1e30f, rmax1 = -1e30f;
        #pragma unroll
        for (int n = 0; n < 2; n++) {
            int key = kq*16 + n*8 + (lane & 3)*2;
            const float* bp = bias_s + h*1088 + r0*68 + key;
            c[n][0] += bp[0];       c[n][1] += bp[1];
            c[n][2] += bp[8*68];    c[n][3] += bp[8*68 + 1];
            rmax0 = fmaxf(rmax0, fmaxf(c[n][0], c[n][1]));
            rmax1 = fmaxf(rmax1, fmaxf(c[n][2], c[n][3]));
        }
        rmax0 = fmaxf(rmax0, __shfl_xor_sync(0xffffffffu, rmax0, 1));
        rmax0 = fmaxf(rmax0, __shfl_xor_sync(0xffffffffu, rmax0, 2));
        rmax1 = fmaxf(rmax1, __shfl_xor_sync(0xffffffffu, rmax1, 1));
        rmax1 = fmaxf(rmax1, __shfl_xor_sync(0xffffffffu, rmax1, 2));
        float M0n = fmaxf(m0, rmax0), M1n = fmaxf(m1, rmax1);
        float cor0 = __expf(m0 - M0n), cor1 = __expf(m1 - M1n);
        m0 = M0n; m1 = M1n;
        l0 *= cor0; l1 *= cor1;
        #pragma unroll
        for (int nd = 0; nd < 4; nd++) {
            o[nd][0] *= cor0; o[nd][1] *= cor0;
            o[nd][2] *= cor1; o[nd][3] *= cor1;
        }
        // exp + pack P to bf16 A-fragment
        float s0 = 0.f, s1 = 0.f;
        uint32_t pa2[4];
        #pragma unroll
        for (int n = 0; n < 2; n++) {
            float p0 = __expf(c[n][0] - m0), p1 = __expf(c[n][1] - m0);
            float p2 = __expf(c[n][2] - m1), p3 = __expf(c[n][3] - m1);
            s0 += p0 + p1; s1 += p2 + p3;
            pa2[n*2 + 0] = packbf(p0, p1);
            pa2[n*2 + 1] = packbf(p2, p3);
        }
        // NOTE frag order must be a0=rows0-7/k0-7, a1=rows8-15/k0-7, a2=rows0-7/k8-15, a3=rows8-15/k8-15
        { uint32_t t = pa2[1]; pa2[1] = pa2[1]; (void)t; } // a-order already: [p(n0,r0) p(n0,r1) p(n1,r0) p(n1,r1)]
        s0 += __shfl_xor_sync(0xffffffffu, s0, 1);
        s0 += __shfl_xor_sync(0xffffffffu, s0, 2);
        s1 += __shfl_xor_sync(0xffffffffu, s1, 1);
        s1 += __shfl_xor_sync(0xffffffffu, s1, 2);
        l0 += s0; l1 += s1;
        // ---- P @ V ----
        #pragma unroll
        for (int vp = 0; vp < 2; vp++) {
            uint32_t b[4];
            ldmx4t(b, vaddr[vp]);
            mma16816(o[vp*2 + 0], pa2, b + 0);
            mma16816(o[vp*2 + 1], pa2, b + 2);
        }
        __syncthreads();
    }

    // ---- combine the 4 key-quarter warps per head ----
    if ((lane & 3) == 0) {
        stat_s[(wid*16 + r0    )*2 + 0] = m0;
        stat_s[(wid*16 + r0    )*2 + 1] = l0;
        stat_s[(wid*16 + r0 + 8)*2 + 0] = m1;
        stat_s[(wid*16 + r0 + 8)*2 + 1] = l1;
    }
    __syncthreads();
    float M0 = -1e30f, M1 = -1e30f;
    #pragma unroll
    for (int q = 0; q < 4; q++) {
        M0 = fmaxf(M0, stat_s[((q*4 + h)*16 + r0    )*2]);
        M1 = fmaxf(M1, stat_s[((q*4 + h)*16 + r0 + 8)*2]);
    }
    float L0 = 0.f, L1 = 0.f;
    #pragma unroll
    for (int q = 0; q < 4; q++) {
        L0 += stat_s[((q*4+h)*16 + r0    )*2 + 1] * __expf(stat_s[((q*4+h)*16 + r0    )*2] - M0);
        L1 += stat_s[((q*4+h)*16 + r0 + 8)*2 + 1] * __expf(stat_s[((q*4+h)*16 + r0 + 8)*2] - M1);
    }
    float fac0 = __expf(m0 - M0), fac1 = __expf(m1 - M1);
    #pragma unroll
    for (int nd = 0; nd < 4; nd++) {
        o[nd][0] *= fac0; o[nd][1] *= fac0;
        o[nd][2] *= fac1; o[nd][3] *= fac1;
    }
    // staged O reduction: kq0 writes, kq1/2 add, kq3 finalizes
    #pragma unroll
    for (int ph = 0; ph < 3; ph++) {
        if (kq == ph) {
            #pragma unroll
            for (int nd = 0; nd < 4; nd++) {
                int d0 = nd*8 + (lane & 3)*2;
                float* ob = obuf + h*528 + r0*33 + d0;
                if (ph == 0) {
                    ob[0] = o[nd][0]; ob[1] = o[nd][1];
                    ob[8*33] = o[nd][2]; ob[8*33+1] = o[nd][3];
                } else {
                    ob[0] += o[nd][0]; ob[1] += o[nd][1];
                    ob[8*33] += o[nd][2]; ob[8*33+1] += o[nd][3];
                }
            }
        }
        __syncthreads();
    }
    if (kq == 3) {
        float inv0 = 1.f / L0, inv1 = 1.f / L1;
        int rowa = i0 + r0, rowb = i0 + r0 + 8;
        #pragma unroll
        for (int nd = 0; nd < 4; nd++) {
            int d0 = nd*8 + (lane & 3)*2;
            int col = h*32 + d0;
            const float* ob = obuf + h*528 + r0*33 + d0;
            float v00 = (ob[0]      + o[nd][0]) * inv0;
            float v01 = (ob[1]      + o[nd][1]) * inv0;
            float v10 = (ob[8*33]   + o[nd][2]) * inv1;
            float v11 = (ob[8*33+1] + o[nd][3]) * inv1;
            g_go[(size_t)rowa*CATOM + col    ] = v00 * g_gate[(size_t)rowa*CATOM + col    ];
            g_go[(size_t)rowa*CATOM + col + 1] = v01 * g_gate[(size_t)rowa*CATOM + col + 1];
            g_go[(size_t)rowb*CATOM + col    ] = v10 * g_gate[(size_t)rowb*CATOM + col    ];
            g_go[(size_t)rowb*CATOM + col + 1] = v11 * g_gate[(size_t)rowb*CATOM + col + 1];
        }
    }
}

// ---------------- host launch ----------------
extern "C" void kernel_launch(void* const* d_in, const int* in_sizes, int n_in,
                              void* d_out, int out_size)
{
    const float* ql  = (const float*)d_in[0];
    const float* plm = (const float*)d_in[2];
    const float* beta= (const float*)d_in[3];
    const float* nqw = (const float*)d_in[4];
    const float* nqb = (const float*)d_in[5];
    const float* npw = (const float*)d_in[6];
    const float* npb = (const float*)d_in[7];
    const float* Wq  = (const float*)d_in[8];
    const float* bq  = (const float*)d_in[9];
    const float* Wk  = (const float*)d_in[10];
    const float* Wv  = (const float*)d_in[11];
    const float* Wpb = (const float*)d_in[12];
    const float* Wg  = (const float*)d_in[13];
    const float* Wo  = (const float*)d_in[14];
    const float* tlw = (const float*)d_in[15];
    const float* tlb = (const float*)d_in[16];
    const float* W1  = (const float*)d_in[17];
    const float* b1  = (const float*)d_in[18];
    const float* W2  = (const float*)d_in[19];
    const float* b2  = (const float*)d_in[20];

    float *qn, *go, *ql1, *hh;
    cudaGetSymbolAddress((void**)&qn,  g_qn);
    cudaGetSymbolAddress((void**)&go,  g_go);
    cudaGetSymbolAddress((void**)&ql1, g_ql1);
    cudaGetSymbolAddress((void**)&hh,  g_h);

    cudaFuncSetAttribute(attn_mma, cudaFuncAttributeMaxDynamicSharedMemorySize, ATTN_SMEM);

    // 1. ql_norm
    ln_kernel<<<NATOMS, 128>>>(ql, nqw, nqb, qn);
    // 2. q(bf16,scaled), k(bf16), v(bf16), gate(sigmoid)
    gemm_qkvg<<<dim3(2, 32, 4), 256>>>(Wq, bq, Wk, Wv, Wg);
    // 3. pair-biased flash attention -> g_go = gate * attn_out
    attn_mma<<<NATOMS/16, 512, ATTN_SMEM>>>(plm, beta, npw, npb, Wpb);
    // 4. ql1 = ql + go @ Wo^T
    gemm_nt32<<<dim3(2, 64), 256>>>(go, Wo, nullptr, ql, ql1, CATOM, CATOM);
    // 5. t = LN(ql1)
    ln_kernel<<<NATOMS, 128>>>(ql1, tlw, tlb, qn);
    // 6. h = relu(t @ W1^T + b1)
    gemm_nt<<<dim3(8, 32), 256>>>(qn, W1, b1, nullptr, hh, 4*CATOM, CATOM, 2);
    // 7. out = ql1 + h @ W2^T + b2
    gemm_nt32<<<dim3(2, 64), 256>>>(hh, W2, b2, ql1, (float*)d_out, CATOM, 4*CATOM);
}

// round 10
// speedup vs baseline: 1.0050x; 1.0002x over previous
#include <cuda_runtime.h>
#include <cuda_bf16.h>
#include <cstdint>

#define NATOMS 2048
#define CATOM  128

// ---------------- scratch (no allocations allowed) ----------------
__device__ float g_qn  [NATOMS*CATOM];
__device__ __align__(16) __nv_bfloat16 g_qh[NATOMS*CATOM];
__device__ __align__(16) __nv_bfloat16 g_kh[NATOMS*CATOM];
__device__ __align__(16) __nv_bfloat16 g_vh[NATOMS*CATOM];
__device__ float g_gate[NATOMS*CATOM];
__device__ float g_go  [NATOMS*CATOM];
__device__ float g_ql1 [NATOMS*CATOM];
__device__ float g_h   [NATOMS*4*CATOM];

// ---------------- mma helpers ----------------
__device__ __forceinline__ uint32_t packbf(float lo, float hi){
    uint32_t r; asm("cvt.rn.bf16x2.f32 %0, %1, %2;" : "=r"(r) : "f"(hi), "f"(lo)); return r;
}
__device__ __forceinline__ void mma16816(float* d, const uint32_t* a, const uint32_t* b){
    asm volatile("mma.sync.aligned.m16n8k16.row.col.f32.bf16.bf16.f32 "
        "{%0,%1,%2,%3}, {%4,%5,%6,%7}, {%8,%9}, {%0,%1,%2,%3};"
        : "+f"(d[0]),"+f"(d[1]),"+f"(d[2]),"+f"(d[3])
        : "r"(a[0]),"r"(a[1]),"r"(a[2]),"r"(a[3]), "r"(b[0]),"r"(b[1]));
}
__device__ __forceinline__ void ldmx4(uint32_t* r, uint32_t addr){
    asm volatile("ldmatrix.sync.aligned.m8n8.x4.shared.b16 {%0,%1,%2,%3}, [%4];"
        : "=r"(r[0]),"=r"(r[1]),"=r"(r[2]),"=r"(r[3]) : "r"(addr));
}
__device__ __forceinline__ void ldmx4t(uint32_t* r, uint32_t addr){
    asm volatile("ldmatrix.sync.aligned.m8n8.x4.trans.shared.b16 {%0,%1,%2,%3}, [%4];"
        : "=r"(r[0]),"=r"(r[1]),"=r"(r[2]),"=r"(r[3]) : "r"(addr));
}
// byte offset of (row, 16B-chunk): rows of 128 bf16 (256B), XOR swizzle
__device__ __forceinline__ uint32_t swz(int row, int ch){
    return (uint32_t)(row*256 + (((ch ^ (row & 7)) & 15) << 4));
}

// ---------------- LayerNorm over C=128 ----------------
__global__ __launch_bounds__(128) void ln_kernel(
    const float* __restrict__ x, const float* __restrict__ w,
    const float* __restrict__ b, float* __restrict__ y)
{
    int row = blockIdx.x;
    int t = threadIdx.x;
    float v = x[(size_t)row*CATOM + t];
    float s = v, s2 = v*v;
    #pragma unroll
    for (int o = 16; o > 0; o >>= 1) {
        s  += __shfl_xor_sync(0xffffffffu, s,  o);
        s2 += __shfl_xor_sync(0xffffffffu, s2, o);
    }
    __shared__ float ps[4], ps2[4];
    int warp = t >> 5;
    if ((t & 31) == 0) { ps[warp] = s; ps2[warp] = s2; }
    __syncthreads();
    float sum  = ps[0]  + ps[1]  + ps[2]  + ps[3];
    float sum2 = ps2[0] + ps2[1] + ps2[2] + ps2[3];
    float mu   = sum  * (1.f/CATOM);
    float var  = sum2 * (1.f/CATOM) - mu*mu;
    float rstd = rsqrtf(var + 1e-5f);
    y[(size_t)row*CATOM + t] = (v - mu) * rstd * w[t] + b[t];
}

// ---------------- fp32 GEMM core: 64x64 tile, C = A @ B^T ----------------
__device__ __forceinline__ void gemm_core64(
    const float* __restrict__ A, const float* __restrict__ B,
    int K, float acc[4][4], float As[16][68], float Bs[16][68])
{
    const int tid = threadIdx.x;
    const int tx = tid & 15, ty = tid >> 4;
    const int m0 = blockIdx.y * 64, n0 = blockIdx.x * 64;
    const int row = tid >> 2;
    const int c4  = (tid & 3) * 4;
    for (int k0 = 0; k0 < K; k0 += 16) {
        float4 a  = *(const float4*)&A[(size_t)(m0+row)*K + k0 + c4];
        float4 bb = *(const float4*)&B[(size_t)(n0+row)*K + k0 + c4];
        As[c4+0][row] = a.x;  As[c4+1][row] = a.y;  As[c4+2][row] = a.z;  As[c4+3][row] = a.w;
        Bs[c4+0][row] = bb.x; Bs[c4+1][row] = bb.y; Bs[c4+2][row] = bb.z; Bs[c4+3][row] = bb.w;
        __syncthreads();
        #pragma unroll
        for (int kk = 0; kk < 16; kk++) {
            float av[4], bv[4];
            #pragma unroll
            for (int i = 0; i < 4; i++) { av[i] = As[kk][ty + 16*i]; bv[i] = Bs[kk][tx + 16*i]; }
            #pragma unroll
            for (int i = 0; i < 4; i++)
                #pragma unroll
                for (int j = 0; j < 4; j++)
                    acc[i][j] = fmaf(av[i], bv[j], acc[i][j]);
        }
        __syncthreads();
    }
}

// 64x64-tile GEMM (W1): op 2 = relu
__global__ __launch_bounds__(256) void gemm_nt(
    const float* __restrict__ A, const float* __restrict__ B,
    const float* __restrict__ bias, const float* __restrict__ resid,
    float* __restrict__ C, int N, int K, int op)
{
    __shared__ float As[16][68];
    __shared__ float Bs[16][68];
    float acc[4][4];
    #pragma unroll
    for (int i = 0; i < 4; i++)
        #pragma unroll
        for (int j = 0; j < 4; j++) acc[i][j] = 0.f;
    gemm_core64(A, B, K, acc, As, Bs);
    const int tid = threadIdx.x;
    const int tx = tid & 15, ty = tid >> 4;
    const int m0 = blockIdx.y * 64, n0 = blockIdx.x * 64;
    #pragma unroll
    for (int i = 0; i < 4; i++) {
        int mm = m0 + ty + 16*i;
        #pragma unroll
        for (int j = 0; j < 4; j++) {
            int nn = n0 + tx + 16*j;
            float v = acc[i][j];
            if (bias)    v += bias[nn];
            if (op == 2) v = fmaxf(v, 0.f);
            if (resid)   v += resid[(size_t)mm*N + nn];
            C[(size_t)mm*N + nn] = v;
        }
    }
}

// QKVG projection with bf16 epilogues (q pre-scaled by 1/sqrt(32))
__global__ __launch_bounds__(256) void gemm_qkvg(
    const float* __restrict__ Wq, const float* __restrict__ bq,
    const float* __restrict__ Wk, const float* __restrict__ Wv,
    const float* __restrict__ Wg)
{
    __shared__ float As[16][68];
    __shared__ float Bs[16][68];
    int z = blockIdx.z;
    const float* B = (z==0) ? Wq : (z==1) ? Wk : (z==2) ? Wv : Wg;
    float acc[4][4];
    #pragma unroll
    for (int i = 0; i < 4; i++)
        #pragma unroll
        for (int j = 0; j < 4; j++) acc[i][j] = 0.f;
    gemm_core64(g_qn, B, CATOM, acc, As, Bs);
    const int tid = threadIdx.x;
    const int tx = tid & 15, ty = tid >> 4;
    const int m0 = blockIdx.y * 64, n0 = blockIdx.x * 64;
    #pragma unroll
    for (int i = 0; i < 4; i++) {
        int mm = m0 + ty + 16*i;
        #pragma unroll
        for (int j = 0; j < 4; j++) {
            int nn = n0 + tx + 16*j;
            float v = acc[i][j];
            size_t idx = (size_t)mm*CATOM + nn;
            if (z == 0)      g_qh[idx] = __float2bfloat16((v + bq[nn]) * 0.17677669529663687f);
            else if (z == 1) g_kh[idx] = __float2bfloat16(v);
            else if (z == 2) g_vh[idx] = __float2bfloat16(v);
            else             g_gate[idx] = 1.f / (1.f + __expf(-v));
        }
    }
}

// 32x64-tile GEMM for N=128 epilogue GEMMs (128 CTAs)
__global__ __launch_bounds__(256) void gemm_nt32(
    const float* __restrict__ A, const float* __restrict__ B,
    const float* __restrict__ bias, const float* __restrict__ resid,
    float* __restrict__ C, int N, int K)
{
    __shared__ float As[16][36];
    __shared__ float Bs[16][68];
    const int tid = threadIdx.x;
    const int tx = tid & 15, ty = tid >> 4;
    const int m0 = blockIdx.y * 32, n0 = blockIdx.x * 64;
    float acc[2][4];
    #pragma unroll
    for (int i = 0; i < 2; i++)
        #pragma unroll
        for (int j = 0; j < 4; j++) acc[i][j] = 0.f;
    const int arow = tid >> 2;
    const int c4   = (tid & 3) * 4;
    for (int k0 = 0; k0 < K; k0 += 16) {
        if (tid < 128) {
            float4 a = *(const float4*)&A[(size_t)(m0+arow)*K + k0 + c4];
            As[c4+0][arow] = a.x; As[c4+1][arow] = a.y; As[c4+2][arow] = a.z; As[c4+3][arow] = a.w;
        }
        float4 bb = *(const float4*)&B[(size_t)(n0+arow)*K + k0 + c4];
        Bs[c4+0][arow] = bb.x; Bs[c4+1][arow] = bb.y; Bs[c4+2][arow] = bb.z; Bs[c4+3][arow] = bb.w;
        __syncthreads();
        #pragma unroll
        for (int kk = 0; kk < 16; kk++) {
            float a0 = As[kk][ty], a1 = As[kk][ty+16];
            float bv[4];
            #pragma unroll
            for (int j = 0; j < 4; j++) bv[j] = Bs[kk][tx + 16*j];
            #pragma unroll
            for (int j = 0; j < 4; j++) {
                acc[0][j] = fmaf(a0, bv[j], acc[0][j]);
                acc[1][j] = fmaf(a1, bv[j], acc[1][j]);
            }
        }
        __syncthreads();
    }
    #pragma unroll
    for (int i = 0; i < 2; i++) {
        int mm = m0 + ty + 16*i;
        #pragma unroll
        for (int j = 0; j < 4; j++) {
            int nn = n0 + tx + 16*j;
            float v = acc[i][j];
            if (bias)  v += bias[nn];
            if (resid) v += resid[(size_t)mm*N + nn];
            C[(size_t)mm*N + nn] = v;
        }
    }
}

// ---------------- tensor-core flash attention with pair bias ----------------
// dynamic smem layout (bytes)
#define KS_OFF    0u        // 64*256      = 16384
#define VS_OFF    16384u    // 64*256      = 16384
#define QS_OFF    32768u    // 16*256      = 4096
#define BIAS_OFF  36864u    // 4*16*68*4   = 17408
#define OBUF_OFF  54272u    // 4*16*33*4   = 8448
#define WW_OFF    62720u    // 64*4        = 256
#define WSUM_OFF  62976u
#define WCS_OFF   62992u
#define STAT_OFF  63008u    // 16*16*2*4   = 2048
#define ATTN_SMEM 65056u

__global__ __launch_bounds__(512,1) void attn_mma(
    const float* __restrict__ plm,  const float* __restrict__ beta,
    const float* __restrict__ npw,  const float* __restrict__ npb,
    const float* __restrict__ Wpb)
{
    extern __shared__ char smem_raw[];
    char* k_sb = smem_raw + KS_OFF;
    char* v_sb = smem_raw + VS_OFF;
    char* q_sb = smem_raw + QS_OFF;
    float* bias_s = (float*)(smem_raw + BIAS_OFF);
    float* obuf   = (float*)(smem_raw + OBUF_OFF);
    float* ww_s   = (float*)(smem_raw + WW_OFF);
    float* wsum_s = (float*)(smem_raw + WSUM_OFF);
    float* wcs_s  = (float*)(smem_raw + WCS_OFF);
    float* stat_s = (float*)(smem_raw + STAT_OFF);   // [16 warps][16 rows][2]

    const int tid  = threadIdx.x;
    const int lane = tid & 31, wid = tid >> 5;
    const int h = wid & 3, kq = wid >> 2;
    const int i0 = blockIdx.x * 16;

    if (tid < 64) ww_s[tid] = npw[tid & 15] * Wpb[tid];
    if (tid < 4) {
        float sw = 0.f, sc = 0.f;
        #pragma unroll
        for (int c = 0; c < 16; c++) {
            float t = npw[c] * Wpb[tid*16 + c];
            sw += t;
            sc += npb[c] * Wpb[tid*16 + c];
        }
        wsum_s[tid] = sw; wcs_s[tid] = sc;
    }
    // stage Q tile
    if (tid < 256) {
        int row = tid >> 4, ch = tid & 15;
        *(uint4*)(q_sb + swz(row, ch)) = *(const uint4*)&g_qh[(size_t)(i0+row)*CATOM + ch*8];
    }
    __syncthreads();

    // Q A-fragments (persist)
    uint32_t qa[2][4];
    {
        uint32_t qb = (uint32_t)__cvta_generic_to_shared(q_sb);
        int row = (lane & 7) + ((lane >> 3) & 1) * 8;
        #pragma unroll
        for (int kc = 0; kc < 2; kc++)
            ldmx4(qa[kc], qb + swz(row, h*4 + kc*2 + (lane >> 4)));
    }
    // K/V ldmatrix addresses (fixed across tiles)
    uint32_t kaddr[2], vaddr[2];
    {
        uint32_t kb = (uint32_t)__cvta_generic_to_shared(k_sb);
        uint32_t vb = (uint32_t)__cvta_generic_to_shared(v_sb);
        int krow = kq*16 + (lane & 7) + ((lane >> 4) & 1) * 8;
        int vrow = kq*16 + (lane & 7) + ((lane >> 3) & 1) * 8;
        #pragma unroll
        for (int kc = 0; kc < 2; kc++) kaddr[kc] = kb + swz(krow, h*4 + kc*2 + ((lane >> 3) & 1));
        #pragma unroll
        for (int vp = 0; vp < 2; vp++) vaddr[vp] = vb + swz(vrow, h*4 + vp*2 + (lane >> 4));
    }

    const int r0 = lane >> 2;        // fragment row (0..7); second row = r0+8
    float m0 = -1e30f, m1 = -1e30f, l0 = 0.f, l1 = 0.f;
    float o[4][4];
    #pragma unroll
    for (int nd = 0; nd < 4; nd++)
        #pragma unroll
        for (int e = 0; e < 4; e++) o[nd][e] = 0.f;

    for (int jt = 0; jt < 32; jt++) {
        const int j0 = jt * 64;
        // ---- stage K/V (64 keys) ----
        #pragma unroll
        for (int s = 0; s < 2; s++) {
            int sl = tid + s*512;
            int row = sl >> 4, ch = sl & 15;
            uint32_t off = swz(row, ch);
            *(uint4*)(k_sb + off) = *(const uint4*)&g_kh[(size_t)(j0+row)*CATOM + ch*8];
            *(uint4*)(v_sb + off) = *(const uint4*)&g_vh[(size_t)(j0+row)*CATOM + ch*8];
        }
        // ---- pair bias: 2 pairs per thread, loads front-batched ----
        {
            int ia = tid, ib = tid + 512;
            int ra = ia >> 6, ka = ia & 63;
            int rb = ib >> 6, kb2 = ib & 63;
            const float4* pa_ = (const float4*)(plm + ((size_t)(i0+ra)*NATOMS + (j0+ka))*16);
            const float4* pb_ = (const float4*)(plm + ((size_t)(i0+rb)*NATOMS + (j0+kb2))*16);
            float4 xa[4], xb[4];
            #pragma unroll
            for (int t = 0; t < 4; t++) { xa[t] = pa_[t]; xb[t] = pb_[t]; }
            float bma = beta[(size_t)(i0+ra)*NATOMS + j0 + ka];
            float bmb = beta[(size_t)(i0+rb)*NATOMS + j0 + kb2];
            #pragma unroll
            for (int pp = 0; pp < 2; pp++) {
                float4* x4 = pp ? xb : xa;
                float bm  = pp ? bmb : bma;
                int row   = pp ? rb : ra;
                int key   = pp ? kb2 : ka;
                float sum = 0.f, sum2 = 0.f;
                #pragma unroll
                for (int t = 0; t < 4; t++) {
                    sum += x4[t].x + x4[t].y + x4[t].z + x4[t].w;
                    sum2 = fmaf(x4[t].x, x4[t].x, sum2);
                    sum2 = fmaf(x4[t].y, x4[t].y, sum2);
                    sum2 = fmaf(x4[t].z, x4[t].z, sum2);
                    sum2 = fmaf(x4[t].w, x4[t].w, sum2);
                }
                float mu   = sum * 0.0625f;
                float rstd = rsqrtf(fmaf(-mu, mu, sum2 * 0.0625f) + 1e-5f);
                #pragma unroll
                for (int hh = 0; hh < 4; hh++) {
                    float d = 0.f;
                    #pragma unroll
                    for (int t = 0; t < 4; t++) {
                        float4 w4 = ((const float4*)ww_s)[hh*4 + t];
                        d = fmaf(x4[t].x, w4.x, d);
                        d = fmaf(x4[t].y, w4.y, d);
                        d = fmaf(x4[t].z, w4.z, d);
                        d = fmaf(x4[t].w, w4.w, d);
                    }
                    bias_s[hh*1088 + row*68 + key] =
                        fmaf(rstd, d - mu*wsum_s[hh], wcs_s[hh] + bm);
                }
            }
        }
        __syncthreads();

        // ---- QK^T : 16 rows x 16 keys for this warp ----
        float c[2][4];
        #pragma unroll
        for (int n = 0; n < 2; n++)
            #pragma unroll
            for (int e = 0; e < 4; e++) c[n][e] = 0.f;
        #pragma unroll
        for (int kc = 0; kc < 2; kc++) {
            uint32_t b[4];
            ldmx4(b, kaddr[kc]);
            mma16816(c[0], qa[kc], b + 0);
            mma16816(c[1], qa[kc], b + 2);
        }
        // add pair bias + beta
        float rmax0 = -1e30f, rmax1 = -1e30f;
        #pragma unroll
        for (int n = 0; n < 2; n++) {
            int key = kq*16 + n*8 + (lane & 3)*2;
            const float* bp = bias_s + h*1088 + r0*68 + key;
            c[n][0] += bp[0];       c[n][1] += bp[1];
            c[n][2] += bp[8*68];    c[n][3] += bp[8*68 + 1];
            rmax0 = fmaxf(rmax0, fmaxf(c[n][0], c[n][1]));
            rmax1 = fmaxf(rmax1, fmaxf(c[n][2], c[n][3]));
        }
        rmax0 = fmaxf(rmax0, __shfl_xor_sync(0xffffffffu, rmax0, 1));
        rmax0 = fmaxf(rmax0, __shfl_xor_sync(0xffffffffu, rmax0, 2));
        rmax1 = fmaxf(rmax1, __shfl_xor_sync(0xffffffffu, rmax1, 1));
        rmax1 = fmaxf(rmax1, __shfl_xor_sync(0xffffffffu, rmax1, 2));
        float M0n = fmaxf(m0, rmax0), M1n = fmaxf(m1, rmax1);
        float cor0 = __expf(m0 - M0n), cor1 = __expf(m1 - M1n);
        m0 = M0n; m1 = M1n;
        l0 *= cor0; l1 *= cor1;
        #pragma unroll
        for (int nd = 0; nd < 4; nd++) {
            o[nd][0] *= cor0; o[nd][1] *= cor0;
            o[nd][2] *= cor1; o[nd][3] *= cor1;
        }
        // exp + pack P to bf16 A-fragment
        float s0 = 0.f, s1 = 0.f;
        uint32_t pa2[4];
        #pragma unroll
        for (int n = 0; n < 2; n++) {
            float p0 = __expf(c[n][0] - m0), p1 = __expf(c[n][1] - m0);
            float p2 = __expf(c[n][2] - m1), p3 = __expf(c[n][3] - m1);
            s0 += p0 + p1; s1 += p2 + p3;
            pa2[n*2 + 0] = packbf(p0, p1);
            pa2[n*2 + 1] = packbf(p2, p3);
        }
        // NOTE frag order must be a0=rows0-7/k0-7, a1=rows8-15/k0-7, a2=rows0-7/k8-15, a3=rows8-15/k8-15
        { uint32_t t = pa2[1]; pa2[1] = pa2[1]; (void)t; } // a-order already: [p(n0,r0) p(n0,r1) p(n1,r0) p(n1,r1)]
        s0 += __shfl_xor_sync(0xffffffffu, s0, 1);
        s0 += __shfl_xor_sync(0xffffffffu, s0, 2);
        s1 += __shfl_xor_sync(0xffffffffu, s1, 1);
        s1 += __shfl_xor_sync(0xffffffffu, s1, 2);
        l0 += s0; l1 += s1;
        // ---- P @ V ----
        #pragma unroll
        for (int vp = 0; vp < 2; vp++) {
            uint32_t b[4];
            ldmx4t(b, vaddr[vp]);
            mma16816(o[vp*2 + 0], pa2, b + 0);
            mma16816(o[vp*2 + 1], pa2, b + 2);
        }
        __syncthreads();
    }

    // ---- combine the 4 key-quarter warps per head ----
    if ((lane & 3) == 0) {
        stat_s[(wid*16 + r0    )*2 + 0] = m0;
        stat_s[(wid*16 + r0    )*2 + 1] = l0;
        stat_s[(wid*16 + r0 + 8)*2 + 0] = m1;
        stat_s[(wid*16 + r0 + 8)*2 + 1] = l1;
    }
    __syncthreads();
    float M0 = -1e30f, M1 = -1e30f;
    #pragma unroll
    for (int q = 0; q < 4; q++) {
        M0 = fmaxf(M0, stat_s[((q*4 + h)*16 + r0    )*2]);
        M1 = fmaxf(M1, stat_s[((q*4 + h)*16 + r0 + 8)*2]);
    }
    float L0 = 0.f, L1 = 0.f;
    #pragma unroll
    for (int q = 0; q < 4; q++) {
        L0 += stat_s[((q*4+h)*16 + r0    )*2 + 1] * __expf(stat_s[((q*4+h)*16 + r0    )*2] - M0);
        L1 += stat_s[((q*4+h)*16 + r0 + 8)*2 + 1] * __expf(stat_s[((q*4+h)*16 + r0 + 8)*2] - M1);
    }
    float fac0 = __expf(m0 - M0), fac1 = __expf(m1 - M1);
    #pragma unroll
    for (int nd = 0; nd < 4; nd++) {
        o[nd][0] *= fac0; o[nd][1] *= fac0;
        o[nd][2] *= fac1; o[nd][3] *= fac1;
    }
    // staged O reduction: kq0 writes, kq1/2 add, kq3 finalizes
    #pragma unroll
    for (int ph = 0; ph < 3; ph++) {
        if (kq == ph) {
            #pragma unroll
            for (int nd = 0; nd < 4; nd++) {
                int d0 = nd*8 + (lane & 3)*2;
                float* ob = obuf + h*528 + r0*33 + d0;
                if (ph == 0) {
                    ob[0] = o[nd][0]; ob[1] = o[nd][1];
                    ob[8*33] = o[nd][2]; ob[8*33+1] = o[nd][3];
                } else {
                    ob[0] += o[nd][0]; ob[1] += o[nd][1];
                    ob[8*33] += o[nd][2]; ob[8*33+1] += o[nd][3];
                }
            }
        }
        __syncthreads();
    }
    if (kq == 3) {
        float inv0 = 1.f / L0, inv1 = 1.f / L1;
        int rowa = i0 + r0, rowb = i0 + r0 + 8;
        #pragma unroll
        for (int nd = 0; nd < 4; nd++) {
            int d0 = nd*8 + (lane & 3)*2;
            int col = h*32 + d0;
            const float* ob = obuf + h*528 + r0*33 + d0;
            float v00 = (ob[0]      + o[nd][0]) * inv0;
            float v01 = (ob[1]      + o[nd][1]) * inv0;
            float v10 = (ob[8*33]   + o[nd][2]) * inv1;
            float v11 = (ob[8*33+1] + o[nd][3]) * inv1;
            g_go[(size_t)rowa*CATOM + col    ] = v00 * g_gate[(size_t)rowa*CATOM + col    ];
            g_go[(size_t)rowa*CATOM + col + 1] = v01 * g_gate[(size_t)rowa*CATOM + col + 1];
            g_go[(size_t)rowb*CATOM + col    ] = v10 * g_gate[(size_t)rowb*CATOM + col    ];
            g_go[(size_t)rowb*CATOM + col + 1] = v11 * g_gate[(size_t)rowb*CATOM + col + 1];
        }
    }
}

// ---------------- host launch ----------------
extern "C" void kernel_launch(void* const* d_in, const int* in_sizes, int n_in,
                              void* d_out, int out_size)
{
    const float* ql  = (const float*)d_in[0];
    const float* plm = (const float*)d_in[2];
    const float* beta= (const float*)d_in[3];
    const float* nqw = (const float*)d_in[4];
    const float* nqb = (const float*)d_in[5];
    const float* npw = (const float*)d_in[6];
    const float* npb = (const float*)d_in[7];
    const float* Wq  = (const float*)d_in[8];
    const float* bq  = (const float*)d_in[9];
    const float* Wk  = (const float*)d_in[10];
    const float* Wv  = (const float*)d_in[11];
    const float* Wpb = (const float*)d_in[12];
    const float* Wg  = (const float*)d_in[13];
    const float* Wo  = (const float*)d_in[14];
    const float* tlw = (const float*)d_in[15];
    const float* tlb = (const float*)d_in[16];
    const float* W1  = (const float*)d_in[17];
    const float* b1  = (const float*)d_in[18];
    const float* W2  = (const float*)d_in[19];
    const float* b2  = (const float*)d_in[20];

    float *qn, *go, *ql1, *hh;
    cudaGetSymbolAddress((void**)&qn,  g_qn);
    cudaGetSymbolAddress((void**)&go,  g_go);
    cudaGetSymbolAddress((void**)&ql1, g_ql1);
    cudaGetSymbolAddress((void**)&hh,  g_h);

    cudaFuncSetAttribute(attn_mma, cudaFuncAttributeMaxDynamicSharedMemorySize, ATTN_SMEM);

    // 1. ql_norm
    ln_kernel<<<NATOMS, 128>>>(ql, nqw, nqb, qn);
    // 2. q(bf16,scaled), k(bf16), v(bf16), gate(sigmoid)
    gemm_qkvg<<<dim3(2, 32, 4), 256>>>(Wq, bq, Wk, Wv, Wg);
    // 3. pair-biased flash attention -> g_go = gate * attn_out
    attn_mma<<<NATOMS/16, 512, ATTN_SMEM>>>(plm, beta, npw, npb, Wpb);
    // 4. ql1 = ql + go @ Wo^T
    gemm_nt32<<<dim3(2, 64), 256>>>(go, Wo, nullptr, ql, ql1, CATOM, CATOM);
    // 5. t = LN(ql1)
    ln_kernel<<<NATOMS, 128>>>(ql1, tlw, tlb, qn);
    // 6. h = relu(t @ W1^T + b1)
    gemm_nt<<<dim3(8, 32), 256>>>(qn, W1, b1, nullptr, hh, 4*CATOM, CATOM, 2);
    // 7. out = ql1 + h @ W2^T + b2
    gemm_nt32<<<dim3(2, 64), 256>>>(hh, W2, b2, ql1, (float*)d_out, CATOM, 4*CATOM);
}

// round 11
// speedup vs baseline: 1.0102x; 1.0052x over previous
#include <cuda_runtime.h>
#include <cuda_bf16.h>
#include <cstdint>

#define NATOMS 2048
#define CATOM  128

// ---------------- scratch (no allocations allowed) ----------------
__device__ float g_qn  [NATOMS*CATOM];
__device__ __align__(16) __nv_bfloat16 g_qh[NATOMS*CATOM];
__device__ __align__(16) __nv_bfloat16 g_kh[NATOMS*CATOM];
__device__ __align__(16) __nv_bfloat16 g_vh[NATOMS*CATOM];
__device__ float g_gate[NATOMS*CATOM];
__device__ float g_go  [NATOMS*CATOM];
__device__ float g_ql1 [NATOMS*CATOM];
__device__ float g_h   [NATOMS*4*CATOM];

// ---------------- mma helpers ----------------
__device__ __forceinline__ uint32_t packbf(float lo, float hi){
    uint32_t r; asm("cvt.rn.bf16x2.f32 %0, %1, %2;" : "=r"(r) : "f"(hi), "f"(lo)); return r;
}
__device__ __forceinline__ void mma16816(float* d, const uint32_t* a, const uint32_t* b){
    asm volatile("mma.sync.aligned.m16n8k16.row.col.f32.bf16.bf16.f32 "
        "{%0,%1,%2,%3}, {%4,%5,%6,%7}, {%8,%9}, {%0,%1,%2,%3};"
        : "+f"(d[0]),"+f"(d[1]),"+f"(d[2]),"+f"(d[3])
        : "r"(a[0]),"r"(a[1]),"r"(a[2]),"r"(a[3]), "r"(b[0]),"r"(b[1]));
}
__device__ __forceinline__ void ldmx4(uint32_t* r, uint32_t addr){
    asm volatile("ldmatrix.sync.aligned.m8n8.x4.shared.b16 {%0,%1,%2,%3}, [%4];"
        : "=r"(r[0]),"=r"(r[1]),"=r"(r[2]),"=r"(r[3]) : "r"(addr));
}
__device__ __forceinline__ void ldmx4t(uint32_t* r, uint32_t addr){
    asm volatile("ldmatrix.sync.aligned.m8n8.x4.trans.shared.b16 {%0,%1,%2,%3}, [%4];"
        : "=r"(r[0]),"=r"(r[1]),"=r"(r[2]),"=r"(r[3]) : "r"(addr));
}
// byte offset of (row, 16B-chunk): rows of 128 bf16 (256B), XOR swizzle
__device__ __forceinline__ uint32_t swz(int row, int ch){
    return (uint32_t)(row*256 + (((ch ^ (row & 7)) & 15) << 4));
}

// ---------------- LayerNorm over C=128 ----------------
__global__ __launch_bounds__(128) void ln_kernel(
    const float* __restrict__ x, const float* __restrict__ w,
    const float* __restrict__ b, float* __restrict__ y)
{
    int row = blockIdx.x;
    int t = threadIdx.x;
    float v = x[(size_t)row*CATOM + t];
    float s = v, s2 = v*v;
    #pragma unroll
    for (int o = 16; o > 0; o >>= 1) {
        s  += __shfl_xor_sync(0xffffffffu, s,  o);
        s2 += __shfl_xor_sync(0xffffffffu, s2, o);
    }
    __shared__ float ps[4], ps2[4];
    int warp = t >> 5;
    if ((t & 31) == 0) { ps[warp] = s; ps2[warp] = s2; }
    __syncthreads();
    float sum  = ps[0]  + ps[1]  + ps[2]  + ps[3];
    float sum2 = ps2[0] + ps2[1] + ps2[2] + ps2[3];
    float mu   = sum  * (1.f/CATOM);
    float var  = sum2 * (1.f/CATOM) - mu*mu;
    float rstd = rsqrtf(var + 1e-5f);
    y[(size_t)row*CATOM + t] = (v - mu) * rstd * w[t] + b[t];
}

// ---------------- fp32 GEMM core: 64x64 tile, C = A @ B^T ----------------
__device__ __forceinline__ void gemm_core64(
    const float* __restrict__ A, const float* __restrict__ B,
    int K, float acc[4][4], float As[16][68], float Bs[16][68])
{
    const int tid = threadIdx.x;
    const int tx = tid & 15, ty = tid >> 4;
    const int m0 = blockIdx.y * 64, n0 = blockIdx.x * 64;
    const int row = tid >> 2;
    const int c4  = (tid & 3) * 4;
    for (int k0 = 0; k0 < K; k0 += 16) {
        float4 a  = *(const float4*)&A[(size_t)(m0+row)*K + k0 + c4];
        float4 bb = *(const float4*)&B[(size_t)(n0+row)*K + k0 + c4];
        As[c4+0][row] = a.x;  As[c4+1][row] = a.y;  As[c4+2][row] = a.z;  As[c4+3][row] = a.w;
        Bs[c4+0][row] = bb.x; Bs[c4+1][row] = bb.y; Bs[c4+2][row] = bb.z; Bs[c4+3][row] = bb.w;
        __syncthreads();
        #pragma unroll
        for (int kk = 0; kk < 16; kk++) {
            float av[4], bv[4];
            #pragma unroll
            for (int i = 0; i < 4; i++) { av[i] = As[kk][ty + 16*i]; bv[i] = Bs[kk][tx + 16*i]; }
            #pragma unroll
            for (int i = 0; i < 4; i++)
                #pragma unroll
                for (int j = 0; j < 4; j++)
                    acc[i][j] = fmaf(av[i], bv[j], acc[i][j]);
        }
        __syncthreads();
    }
}

// 64x64-tile GEMM (W1): op 2 = relu
__global__ __launch_bounds__(256) void gemm_nt(
    const float* __restrict__ A, const float* __restrict__ B,
    const float* __restrict__ bias, const float* __restrict__ resid,
    float* __restrict__ C, int N, int K, int op)
{
    __shared__ float As[16][68];
    __shared__ float Bs[16][68];
    float acc[4][4];
    #pragma unroll
    for (int i = 0; i < 4; i++)
        #pragma unroll
        for (int j = 0; j < 4; j++) acc[i][j] = 0.f;
    gemm_core64(A, B, K, acc, As, Bs);
    const int tid = threadIdx.x;
    const int tx = tid & 15, ty = tid >> 4;
    const int m0 = blockIdx.y * 64, n0 = blockIdx.x * 64;
    #pragma unroll
    for (int i = 0; i < 4; i++) {
        int mm = m0 + ty + 16*i;
        #pragma unroll
        for (int j = 0; j < 4; j++) {
            int nn = n0 + tx + 16*j;
            float v = acc[i][j];
            if (bias)    v += bias[nn];
            if (op == 2) v = fmaxf(v, 0.f);
            if (resid)   v += resid[(size_t)mm*N + nn];
            C[(size_t)mm*N + nn] = v;
        }
    }
}

// QKVG projection with bf16 epilogues (q pre-scaled by 1/sqrt(32))
__global__ __launch_bounds__(256) void gemm_qkvg(
    const float* __restrict__ Wq, const float* __restrict__ bq,
    const float* __restrict__ Wk, const float* __restrict__ Wv,
    const float* __restrict__ Wg)
{
    __shared__ float As[16][68];
    __shared__ float Bs[16][68];
    int z = blockIdx.z;
    const float* B = (z==0) ? Wq : (z==1) ? Wk : (z==2) ? Wv : Wg;
    float acc[4][4];
    #pragma unroll
    for (int i = 0; i < 4; i++)
        #pragma unroll
        for (int j = 0; j < 4; j++) acc[i][j] = 0.f;
    gemm_core64(g_qn, B, CATOM, acc, As, Bs);
    const int tid = threadIdx.x;
    const int tx = tid & 15, ty = tid >> 4;
    const int m0 = blockIdx.y * 64, n0 = blockIdx.x * 64;
    #pragma unroll
    for (int i = 0; i < 4; i++) {
        int mm = m0 + ty + 16*i;
        #pragma unroll
        for (int j = 0; j < 4; j++) {
            int nn = n0 + tx + 16*j;
            float v = acc[i][j];
            size_t idx = (size_t)mm*CATOM + nn;
            if (z == 0)      g_qh[idx] = __float2bfloat16((v + bq[nn]) * 0.17677669529663687f);
            else if (z == 1) g_kh[idx] = __float2bfloat16(v);
            else if (z == 2) g_vh[idx] = __float2bfloat16(v);
            else             g_gate[idx] = 1.f / (1.f + __expf(-v));
        }
    }
}

// 32x64-tile GEMM for N=128 epilogue GEMMs (128 CTAs)
__global__ __launch_bounds__(256) void gemm_nt32(
    const float* __restrict__ A, const float* __restrict__ B,
    const float* __restrict__ bias, const float* __restrict__ resid,
    float* __restrict__ C, int N, int K)
{
    __shared__ float As[16][36];
    __shared__ float Bs[16][68];
    const int tid = threadIdx.x;
    const int tx = tid & 15, ty = tid >> 4;
    const int m0 = blockIdx.y * 32, n0 = blockIdx.x * 64;
    float acc[2][4];
    #pragma unroll
    for (int i = 0; i < 2; i++)
        #pragma unroll
        for (int j = 0; j < 4; j++) acc[i][j] = 0.f;
    const int arow = tid >> 2;
    const int c4   = (tid & 3) * 4;
    for (int k0 = 0; k0 < K; k0 += 16) {
        if (tid < 128) {
            float4 a = *(const float4*)&A[(size_t)(m0+arow)*K + k0 + c4];
            As[c4+0][arow] = a.x; As[c4+1][arow] = a.y; As[c4+2][arow] = a.z; As[c4+3][arow] = a.w;
        }
        float4 bb = *(const float4*)&B[(size_t)(n0+arow)*K + k0 + c4];
        Bs[c4+0][arow] = bb.x; Bs[c4+1][arow] = bb.y; Bs[c4+2][arow] = bb.z; Bs[c4+3][arow] = bb.w;
        __syncthreads();
        #pragma unroll
        for (int kk = 0; kk < 16; kk++) {
            float a0 = As[kk][ty], a1 = As[kk][ty+16];
            float bv[4];
            #pragma unroll
            for (int j = 0; j < 4; j++) bv[j] = Bs[kk][tx + 16*j];
            #pragma unroll
            for (int j = 0; j < 4; j++) {
                acc[0][j] = fmaf(a0, bv[j], acc[0][j]);
                acc[1][j] = fmaf(a1, bv[j], acc[1][j]);
            }
        }
        __syncthreads();
    }
    #pragma unroll
    for (int i = 0; i < 2; i++) {
        int mm = m0 + ty + 16*i;
        #pragma unroll
        for (int j = 0; j < 4; j++) {
            int nn = n0 + tx + 16*j;
            float v = acc[i][j];
            if (bias)  v += bias[nn];
            if (resid) v += resid[(size_t)mm*N + nn];
            C[(size_t)mm*N + nn] = v;
        }
    }
}

// ---------------- tensor-core flash attention with pair bias ----------------
// dynamic smem layout (bytes)
#define KS_OFF    0u        // 64*256      = 16384
#define VS_OFF    16384u    // 64*256      = 16384
#define QS_OFF    32768u    // 16*256      = 4096
#define BIAS_OFF  36864u    // 4*16*68*4   = 17408
#define OBUF_OFF  54272u    // 4*16*33*4   = 8448
#define WW_OFF    62720u    // 64*4        = 256
#define WSUM_OFF  62976u
#define WCS_OFF   62992u
#define STAT_OFF  63008u    // 16*16*2*4   = 2048
#define ATTN_SMEM 65056u

__global__ __launch_bounds__(512,1) void attn_mma(
    const float* __restrict__ plm,  const float* __restrict__ beta,
    const float* __restrict__ npw,  const float* __restrict__ npb,
    const float* __restrict__ Wpb)
{
    extern __shared__ char smem_raw[];
    char* k_sb = smem_raw + KS_OFF;
    char* v_sb = smem_raw + VS_OFF;
    char* q_sb = smem_raw + QS_OFF;
    float* bias_s = (float*)(smem_raw + BIAS_OFF);
    float* obuf   = (float*)(smem_raw + OBUF_OFF);
    float* ww_s   = (float*)(smem_raw + WW_OFF);
    float* wsum_s = (float*)(smem_raw + WSUM_OFF);
    float* wcs_s  = (float*)(smem_raw + WCS_OFF);
    float* stat_s = (float*)(smem_raw + STAT_OFF);   // [16 warps][16 rows][2]

    const int tid  = threadIdx.x;
    const int lane = tid & 31, wid = tid >> 5;
    const int h = wid & 3, kq = wid >> 2;
    const int i0 = blockIdx.x * 16;

    if (tid < 64) ww_s[tid] = npw[tid & 15] * Wpb[tid];
    if (tid < 4) {
        float sw = 0.f, sc = 0.f;
        #pragma unroll
        for (int c = 0; c < 16; c++) {
            float t = npw[c] * Wpb[tid*16 + c];
            sw += t;
            sc += npb[c] * Wpb[tid*16 + c];
        }
        wsum_s[tid] = sw; wcs_s[tid] = sc;
    }
    // stage Q tile
    if (tid < 256) {
        int row = tid >> 4, ch = tid & 15;
        *(uint4*)(q_sb + swz(row, ch)) = *(const uint4*)&g_qh[(size_t)(i0+row)*CATOM + ch*8];
    }
    __syncthreads();

    // Q A-fragments (persist)
    uint32_t qa[2][4];
    {
        uint32_t qb = (uint32_t)__cvta_generic_to_shared(q_sb);
        int row = (lane & 7) + ((lane >> 3) & 1) * 8;
        #pragma unroll
        for (int kc = 0; kc < 2; kc++)
            ldmx4(qa[kc], qb + swz(row, h*4 + kc*2 + (lane >> 4)));
    }
    // K/V ldmatrix addresses (fixed across tiles)
    uint32_t kaddr[2], vaddr[2];
    {
        uint32_t kb = (uint32_t)__cvta_generic_to_shared(k_sb);
        uint32_t vb = (uint32_t)__cvta_generic_to_shared(v_sb);
        int krow = kq*16 + (lane & 7) + ((lane >> 4) & 1) * 8;
        int vrow = kq*16 + (lane & 7) + ((lane >> 3) & 1) * 8;
        #pragma unroll
        for (int kc = 0; kc < 2; kc++) kaddr[kc] = kb + swz(krow, h*4 + kc*2 + ((lane >> 3) & 1));
        #pragma unroll
        for (int vp = 0; vp < 2; vp++) vaddr[vp] = vb + swz(vrow, h*4 + vp*2 + (lane >> 4));
    }

    const int r0 = lane >> 2;        // fragment row (0..7); second row = r0+8
    float m0 = -1e30f, m1 = -1e30f, l0 = 0.f, l1 = 0.f;
    float o[4][4];
    #pragma unroll
    for (int nd = 0; nd < 4; nd++)
        #pragma unroll
        for (int e = 0; e < 4; e++) o[nd][e] = 0.f;

    for (int jt = 0; jt < 32; jt++) {
        const int j0 = jt * 64;
        // ---- stage K/V (64 keys) ----
        #pragma unroll
        for (int s = 0; s < 2; s++) {
            int sl = tid + s*512;
            int row = sl >> 4, ch = sl & 15;
            uint32_t off = swz(row, ch);
            *(uint4*)(k_sb + off) = *(const uint4*)&g_kh[(size_t)(j0+row)*CATOM + ch*8];
            *(uint4*)(v_sb + off) = *(const uint4*)&g_vh[(size_t)(j0+row)*CATOM + ch*8];
        }
        // ---- pair bias: 2 pairs per thread, loads front-batched ----
        {
            int ia = tid, ib = tid + 512;
            int ra = ia >> 6, ka = ia & 63;
            int rb = ib >> 6, kb2 = ib & 63;
            const float4* pa_ = (const float4*)(plm + ((size_t)(i0+ra)*NATOMS + (j0+ka))*16);
            const float4* pb_ = (const float4*)(plm + ((size_t)(i0+rb)*NATOMS + (j0+kb2))*16);
            float4 xa[4], xb[4];
            #pragma unroll
            for (int t = 0; t < 4; t++) { xa[t] = pa_[t]; xb[t] = pb_[t]; }
            float bma = beta[(size_t)(i0+ra)*NATOMS + j0 + ka];
            float bmb = beta[(size_t)(i0+rb)*NATOMS + j0 + kb2];
            #pragma unroll
            for (int pp = 0; pp < 2; pp++) {
                float4* x4 = pp ? xb : xa;
                float bm  = pp ? bmb : bma;
                int row   = pp ? rb : ra;
                int key   = pp ? kb2 : ka;
                float sum = 0.f, sum2 = 0.f;
                #pragma unroll
                for (int t = 0; t < 4; t++) {
                    sum += x4[t].x + x4[t].y + x4[t].z + x4[t].w;
                    sum2 = fmaf(x4[t].x, x4[t].x, sum2);
                    sum2 = fmaf(x4[t].y, x4[t].y, sum2);
                    sum2 = fmaf(x4[t].z, x4[t].z, sum2);
                    sum2 = fmaf(x4[t].w, x4[t].w, sum2);
                }
                float mu   = sum * 0.0625f;
                float rstd = rsqrtf(fmaf(-mu, mu, sum2 * 0.0625f) + 1e-5f);
                #pragma unroll
                for (int hh = 0; hh < 4; hh++) {
                    float d = 0.f;
                    #pragma unroll
                    for (int t = 0; t < 4; t++) {
                        float4 w4 = ((const float4*)ww_s)[hh*4 + t];
                        d = fmaf(x4[t].x, w4.x, d);
                        d = fmaf(x4[t].y, w4.y, d);
                        d = fmaf(x4[t].z, w4.z, d);
                        d = fmaf(x4[t].w, w4.w, d);
                    }
                    bias_s[hh*1088 + row*68 + key] =
                        fmaf(rstd, d - mu*wsum_s[hh], wcs_s[hh] + bm);
                }
            }
        }
        __syncthreads();

        // ---- QK^T : 16 rows x 16 keys for this warp ----
        float c[2][4];
        #pragma unroll
        for (int n = 0; n < 2; n++)
            #pragma unroll
            for (int e = 0; e < 4; e++) c[n][e] = 0.f;
        #pragma unroll
        for (int kc = 0; kc < 2; kc++) {
            uint32_t b[4];
            ldmx4(b, kaddr[kc]);
            mma16816(c[0], qa[kc], b + 0);
            mma16816(c[1], qa[kc], b + 2);
        }
        // add pair bias + beta
        float rmax0 = -1e30f, rmax1 = -1e30f;
        #pragma unroll
        for (int n = 0; n < 2; n++) {
            int key = kq*16 + n*8 + (lane & 3)*2;
            const float* bp = bias_s + h*1088 + r0*68 + key;
            c[n][0] += bp[0];       c[n][1] += bp[1];
            c[n][2] += bp[8*68];    c[n][3] += bp[8*68 + 1];
            rmax0 = fmaxf(rmax0, fmaxf(c[n][0], c[n][1]));
            rmax1 = fmaxf(rmax1, fmaxf(c[n][2], c[n][3]));
        }
        rmax0 = fmaxf(rmax0, __shfl_xor_sync(0xffffffffu, rmax0, 1));
        rmax0 = fmaxf(rmax0, __shfl_xor_sync(0xffffffffu, rmax0, 2));
        rmax1 = fmaxf(rmax1, __shfl_xor_sync(0xffffffffu, rmax1, 1));
        rmax1 = fmaxf(rmax1, __shfl_xor_sync(0xffffffffu, rmax1, 2));
        float M0n = fmaxf(m0, rmax0), M1n = fmaxf(m1, rmax1);
        float cor0 = __expf(m0 - M0n), cor1 = __expf(m1 - M1n);
        m0 = M0n; m1 = M1n;
        l0 *= cor0; l1 *= cor1;
        #pragma unroll
        for (int nd = 0; nd < 4; nd++) {
            o[nd][0] *= cor0; o[nd][1] *= cor0;
            o[nd][2] *= cor1; o[nd][3] *= cor1;
        }
        // exp + pack P to bf16 A-fragment
        float s0 = 0.f, s1 = 0.f;
        uint32_t pa2[4];
        #pragma unroll
        for (int n = 0; n < 2; n++) {
            float p0 = __expf(c[n][0] - m0), p1 = __expf(c[n][1] - m0);
            float p2 = __expf(c[n][2] - m1), p3 = __expf(c[n][3] - m1);
            s0 += p0 + p1; s1 += p2 + p3;
            pa2[n*2 + 0] = packbf(p0, p1);
            pa2[n*2 + 1] = packbf(p2, p3);
        }
        // NOTE frag order must be a0=rows0-7/k0-7, a1=rows8-15/k0-7, a2=rows0-7/k8-15, a3=rows8-15/k8-15
        { uint32_t t = pa2[1]; pa2[1] = pa2[1]; (void)t; } // a-order already: [p(n0,r0) p(n0,r1) p(n1,r0) p(n1,r1)]
        s0 += __shfl_xor_sync(0xffffffffu, s0, 1);
        s0 += __shfl_xor_sync(0xffffffffu, s0, 2);
        s1 += __shfl_xor_sync(0xffffffffu, s1, 1);
        s1 += __shfl_xor_sync(0xffffffffu, s1, 2);
        l0 += s0; l1 += s1;
        // ---- P @ V ----
        #pragma unroll
        for (int vp = 0; vp < 2; vp++) {
            uint32_t b[4];
            ldmx4t(b, vaddr[vp]);
            mma16816(o[vp*2 + 0], pa2, b + 0);
            mma16816(o[vp*2 + 1], pa2, b + 2);
        }
        __syncthreads();
    }

    // ---- combine the 4 key-quarter warps per head ----
    if ((lane & 3) == 0) {
        stat_s[(wid*16 + r0    )*2 + 0] = m0;
        stat_s[(wid*16 + r0    )*2 + 1] = l0;
        stat_s[(wid*16 + r0 + 8)*2 + 0] = m1;
        stat_s[(wid*16 + r0 + 8)*2 + 1] = l1;
    }
    __syncthreads();
    float M0 = -1e30f, M1 = -1e30f;
    #pragma unroll
    for (int q = 0; q < 4; q++) {
        M0 = fmaxf(M0, stat_s[((q*4 + h)*16 + r0    )*2]);
        M1 = fmaxf(M1, stat_s[((q*4 + h)*16 + r0 + 8)*2]);
    }
    float L0 = 0.f, L1 = 0.f;
    #pragma unroll
    for (int q = 0; q < 4; q++) {
        L0 += stat_s[((q*4+h)*16 + r0    )*2 + 1] * __expf(stat_s[((q*4+h)*16 + r0    )*2] - M0);
        L1 += stat_s[((q*4+h)*16 + r0 + 8)*2 + 1] * __expf(stat_s[((q*4+h)*16 + r0 + 8)*2] - M1);
    }
    float fac0 = __expf(m0 - M0), fac1 = __expf(m1 - M1);
    #pragma unroll
    for (int nd = 0; nd < 4; nd++) {
        o[nd][0] *= fac0; o[nd][1] *= fac0;
        o[nd][2] *= fac1; o[nd][3] *= fac1;
    }
    // staged O reduction: kq0 writes, kq1/2 add, kq3 finalizes
    #pragma unroll
    for (int ph = 0; ph < 3; ph++) {
        if (kq == ph) {
            #pragma unroll
            for (int nd = 0; nd < 4; nd++) {
                int d0 = nd*8 + (lane & 3)*2;
                float* ob = obuf + h*528 + r0*33 + d0;
                if (ph == 0) {
                    ob[0] = o[nd][0]; ob[1] = o[nd][1];
                    ob[8*33] = o[nd][2]; ob[8*33+1] = o[nd][3];
                } else {
                    ob[0] += o[nd][0]; ob[1] += o[nd][1];
                    ob[8*33] += o[nd][2]; ob[8*33+1] += o[nd][3];
                }
            }
        }
        __syncthreads();
    }
    if (kq == 3) {
        float inv0 = 1.f / L0, inv1 = 1.f / L1;
        int rowa = i0 + r0, rowb = i0 + r0 + 8;
        #pragma unroll
        for (int nd = 0; nd < 4; nd++) {
            int d0 = nd*8 + (lane & 3)*2;
            int col = h*32 + d0;
            const float* ob = obuf + h*528 + r0*33 + d0;
            float v00 = (ob[0]      + o[nd][0]) * inv0;
            float v01 = (ob[1]      + o[nd][1]) * inv0;
            float v10 = (ob[8*33]   + o[nd][2]) * inv1;
            float v11 = (ob[8*33+1] + o[nd][3]) * inv1;
            g_go[(size_t)rowa*CATOM + col    ] = v00 * g_gate[(size_t)rowa*CATOM + col    ];
            g_go[(size_t)rowa*CATOM + col + 1] = v01 * g_gate[(size_t)rowa*CATOM + col + 1];
            g_go[(size_t)rowb*CATOM + col    ] = v10 * g_gate[(size_t)rowb*CATOM + col    ];
            g_go[(size_t)rowb*CATOM + col + 1] = v11 * g_gate[(size_t)rowb*CATOM + col + 1];
        }
    }
}

// ---------------- host launch ----------------
extern "C" void kernel_launch(void* const* d_in, const int* in_sizes, int n_in,
                              void* d_out, int out_size)
{
    const float* ql  = (const float*)d_in[0];
    const float* plm = (const float*)d_in[2];
    const float* beta= (const float*)d_in[3];
    const float* nqw = (const float*)d_in[4];
    const float* nqb = (const float*)d_in[5];
    const float* npw = (const float*)d_in[6];
    const float* npb = (const float*)d_in[7];
    const float* Wq  = (const float*)d_in[8];
    const float* bq  = (const float*)d_in[9];
    const float* Wk  = (const float*)d_in[10];
    const float* Wv  = (const float*)d_in[11];
    const float* Wpb = (const float*)d_in[12];
    const float* Wg  = (const float*)d_in[13];
    const float* Wo  = (const float*)d_in[14];
    const float* tlw = (const float*)d_in[15];
    const float* tlb = (const float*)d_in[16];
    const float* W1  = (const float*)d_in[17];
    const float* b1  = (const float*)d_in[18];
    const float* W2  = (const float*)d_in[19];
    const float* b2  = (const float*)d_in[20];

    float *qn, *go, *ql1, *hh;
    cudaGetSymbolAddress((void**)&qn,  g_qn);
    cudaGetSymbolAddress((void**)&go,  g_go);
    cudaGetSymbolAddress((void**)&ql1, g_ql1);
    cudaGetSymbolAddress((void**)&hh,  g_h);

    cudaFuncSetAttribute(attn_mma, cudaFuncAttributeMaxDynamicSharedMemorySize, ATTN_SMEM);

    // 1. ql_norm
    ln_kernel<<<NATOMS, 128>>>(ql, nqw, nqb, qn);
    // 2. q(bf16,scaled), k(bf16), v(bf16), gate(sigmoid)
    gemm_qkvg<<<dim3(2, 32, 4), 256>>>(Wq, bq, Wk, Wv, Wg);
    // 3. pair-biased flash attention -> g_go = gate * attn_out
    attn_mma<<<NATOMS/16, 512, ATTN_SMEM>>>(plm, beta, npw, npb, Wpb);
    // 4. ql1 = ql + go @ Wo^T
    gemm_nt32<<<dim3(2, 64), 256>>>(go, Wo, nullptr, ql, ql1, CATOM, CATOM);
    // 5. t = LN(ql1)
    ln_kernel<<<NATOMS, 128>>>(ql1, tlw, tlb, qn);
    // 6. h = relu(t @ W1^T + b1)
    gemm_nt<<<dim3(8, 32), 256>>>(qn, W1, b1, nullptr, hh, 4*CATOM, CATOM, 2);
    // 7. out = ql1 + h @ W2^T + b2
    gemm_nt32<<<dim3(2, 64), 256>>>(hh, W2, b2, ql1, (float*)d_out, CATOM, 4*CATOM);
}